// round 8
// baseline (speedup 1.0000x reference)
#include <cuda_runtime.h>
#include <cuda_fp16.h>

#define NN 100000
#define NE 1600000
#define FIN 128
#define HID 64
#define SCAN_NBLK 98     // ceil(NN/1024)
#define CSR_B 148
#define CSR_T 1024

typedef unsigned int uint32;

// ---------------- scratch (device globals; no allocation allowed) ----------------
__device__ __align__(256) __half2 g_h0h[(size_t)NN * 32];  // gemm out (fp16)
__device__ __align__(256) __half2 g_h1h[(size_t)NN * 32];  // conv1 hidden (fp16)
__device__ __align__(256) float  g_y [(size_t)NN * 16];    // per-node edge-head partials
__device__ __align__(256) float  g_dinv[NN];
__device__ __align__(256) int    g_deg[NN];
__device__ __align__(256) int    g_cursor[NN];
__device__ __align__(256) int    g_rowptr[NN + 1];
__device__ __align__(256) int2   g_srcw[NE];               // {src, bits(dinv[src])}
__device__ __align__(256) int    g_bsums[128];
__device__ int g_barc[8];   // one-shot barrier counters (zero-init; reset by k_agg<false>)

// ---------------- software grid barrier ----------------
__device__ __forceinline__ void gbar(int j) {
    __syncthreads();
    if (threadIdx.x == 0) {
        __threadfence();
        atomicAdd(&g_barc[j], 1);
        volatile int* p = &g_barc[j];
        while (*p < CSR_B) { }
        __threadfence();
    }
    __syncthreads();
}

// ---------------- fused CSR build ----------------
__global__ __launch_bounds__(CSR_T) void k_csr(const int* __restrict__ row,
                                               const int* __restrict__ col) {
    const int tid = threadIdx.x, bid = blockIdx.x;
    const int gt = bid * CSR_T + tid;
    const int gstride = CSR_B * CSR_T;

    for (int i = gt; i < NN; i += gstride) g_deg[i] = 0;
    gbar(0);

    for (int e = gt; e < NE; e += gstride) atomicAdd(&g_deg[col[e]], 1);
    gbar(1);

    int excl = 0;
    int valid = 0;
    if (bid < SCAN_NBLK) {
        int i = bid * CSR_T + tid;
        valid = (i < NN);
        int v = valid ? __ldcg(&g_deg[i]) : 0;
        if (valid) g_dinv[i] = rsqrtf((float)v + 1.0f);   // +1 self-loop
        int lane = tid & 31, wid = tid >> 5;
        int x = v;
        #pragma unroll
        for (int d = 1; d < 32; d <<= 1) {
            int y = __shfl_up_sync(0xffffffffu, x, d);
            if (lane >= d) x += y;
        }
        __shared__ int wsum[32];
        if (lane == 31) wsum[wid] = x;
        __syncthreads();
        if (wid == 0) {
            int s = wsum[lane];
            int sx = s;
            #pragma unroll
            for (int d = 1; d < 32; d <<= 1) {
                int y = __shfl_up_sync(0xffffffffu, sx, d);
                if (lane >= d) sx += y;
            }
            wsum[lane] = sx - s;
        }
        __syncthreads();
        int incl = x + wsum[wid];
        excl = incl - v;
        if (tid == 1023) g_bsums[bid] = incl;
    }
    gbar(2);

    {
        __shared__ int ws[4];
        int v = 0, incl = 0;
        if (bid == 0) {
            if (tid < 128) {
                v = (tid < SCAN_NBLK) ? __ldcg(&g_bsums[tid]) : 0;
                int lane = tid & 31, wid = tid >> 5;
                int x = v;
                #pragma unroll
                for (int d = 1; d < 32; d <<= 1) {
                    int y = __shfl_up_sync(0xffffffffu, x, d);
                    if (lane >= d) x += y;
                }
                if (lane == 31) ws[wid] = x;
                incl = x;
            }
            __syncthreads();
            if (tid < 128) {
                int wid = tid >> 5;
                int off = 0;
                for (int w = 0; w < wid; w++) off += ws[w];
                incl += off;
                if (tid < SCAN_NBLK) g_bsums[tid] = incl - v;
            }
        }
    }
    gbar(3);

    if (bid < SCAN_NBLK && valid) {
        int i = bid * CSR_T + tid;
        int rp = excl + __ldcg(&g_bsums[bid]);
        g_rowptr[i] = rp;
        g_cursor[i] = rp;
    }
    if (bid == 0 && tid == 0) g_rowptr[NN] = NE;
    gbar(4);

    for (int e = gt; e < NE; e += gstride) {
        int c = col[e];
        int r = row[e];
        int p = atomicAdd(&g_cursor[c], 1);
        float dv = __ldcg(&g_dinv[r]);
        g_srcw[p] = make_int2(r, __float_as_int(dv));
    }
}

// ---------------- tensor-core GEMM (smem-staged A) ----------------
// PREMUL=false: g_h0h[r,:] = A[r,:]@W            (no dinv dep -> overlappable with CSR)
// PREMUL=true : g_h0h[r,:] = dinv[r]*(A[r,:]@W)
__device__ __forceinline__ void mma16816(float d[4], uint32 a0, uint32 a1, uint32 a2,
                                         uint32 a3, uint32 b0, uint32 b1) {
    asm volatile(
        "mma.sync.aligned.m16n8k16.row.col.f32.f16.f16.f32 "
        "{%0,%1,%2,%3}, {%4,%5,%6,%7}, {%8,%9}, {%0,%1,%2,%3};"
        : "+f"(d[0]), "+f"(d[1]), "+f"(d[2]), "+f"(d[3])
        : "r"(a0), "r"(a1), "r"(a2), "r"(a3), "r"(b0), "r"(b1));
}

template <int K, bool A_HALF, bool PREMUL>
__global__ __launch_bounds__(128) void k_gemm_mma(const float* __restrict__ Af,
                                                  const float* __restrict__ W) {
    __shared__ __half Wt[64][K + 8];     // W transposed [n][k]
    __shared__ __half Ahs[64][K + 8];    // staged A tile (reused for epilogue staging)

    for (int i = threadIdx.x; i < K * 64; i += 128) {
        int k = i >> 6, n = i & 63;
        Wt[n][k] = __float2half(W[i]);
    }

    const int rbase = blockIdx.x * 64;
    if (A_HALF) {
        const __half* Ah = reinterpret_cast<const __half*>(g_h1h);  // device-side symbol
        const int nvec = 64 * (K / 8);
        #pragma unroll
        for (int it = 0; it < nvec / 128; it++) {
            int i = it * 128 + threadIdx.x;
            int r = i / (K / 8), v = i % (K / 8);
            int R = rbase + r;
            uint4 val = make_uint4(0, 0, 0, 0);
            if (R < NN) val = reinterpret_cast<const uint4*>(Ah + (size_t)R * K)[v];
            reinterpret_cast<uint4*>(&Ahs[r][0])[v] = val;
        }
    } else {
        const int nvec = 64 * (K / 4);
        #pragma unroll
        for (int it = 0; it < nvec / 128; it++) {
            int i = it * 128 + threadIdx.x;
            int r = i / (K / 4), v = i % (K / 4);
            int R = rbase + r;
            float4 f = make_float4(0.f, 0.f, 0.f, 0.f);
            if (R < NN) f = reinterpret_cast<const float4*>(Af + (size_t)R * K)[v];
            __half2 h01 = __floats2half2_rn(f.x, f.y);
            __half2 h23 = __floats2half2_rn(f.z, f.w);
            uint2 pk = make_uint2(*reinterpret_cast<uint32*>(&h01),
                                  *reinterpret_cast<uint32*>(&h23));
            *reinterpret_cast<uint2*>(&Ahs[r][v * 4]) = pk;
        }
    }
    __syncthreads();

    const int warp = threadIdx.x >> 5, lane = threadIdx.x & 31;
    const int gr = lane >> 2;           // 0..7
    const int kc = (lane & 3) * 2;      // 0,2,4,6
    const int lr0 = warp * 16 + gr;
    const int lr1 = lr0 + 8;
    const int R0 = rbase + lr0, R1 = rbase + lr1;

    float d[8][4];
    #pragma unroll
    for (int nt = 0; nt < 8; nt++)
        #pragma unroll
        for (int t = 0; t < 4; t++) d[nt][t] = 0.f;

    #pragma unroll
    for (int q = 0; q < K / 16; q++) {
        int k0 = q * 16 + kc;
        uint32 a0 = *reinterpret_cast<const uint32*>(&Ahs[lr0][k0]);
        uint32 a1 = *reinterpret_cast<const uint32*>(&Ahs[lr1][k0]);
        uint32 a2 = *reinterpret_cast<const uint32*>(&Ahs[lr0][k0 + 8]);
        uint32 a3 = *reinterpret_cast<const uint32*>(&Ahs[lr1][k0 + 8]);
        #pragma unroll
        for (int nt = 0; nt < 8; nt++) {
            int n = nt * 8 + gr;
            uint32 b0 = *reinterpret_cast<const uint32*>(&Wt[n][k0]);
            uint32 b1 = *reinterpret_cast<const uint32*>(&Wt[n][k0 + 8]);
            mma16816(d[nt], a0, a1, a2, a3, b0, b1);
        }
    }

    float dv0 = 1.f, dv1 = 1.f;
    if (PREMUL) {
        dv0 = (R0 < NN) ? g_dinv[R0] : 0.f;
        dv1 = (R1 < NN) ? g_dinv[R1] : 0.f;
    }
    #pragma unroll
    for (int nt = 0; nt < 8; nt++) {
        int c = nt * 8 + kc;
        *reinterpret_cast<__half2*>(&Ahs[lr0][c]) =
            __floats2half2_rn(d[nt][0] * dv0, d[nt][1] * dv0);
        *reinterpret_cast<__half2*>(&Ahs[lr1][c]) =
            __floats2half2_rn(d[nt][2] * dv1, d[nt][3] * dv1);
    }
    __syncwarp();
    __half* outp = reinterpret_cast<__half*>(g_h0h);
    #pragma unroll
    for (int rr = 0; rr < 16; rr++) {
        int R = rbase + warp * 16 + rr;
        if (R < NN) {
            uint32 v = reinterpret_cast<const uint32*>(&Ahs[warp * 16 + rr][0])[lane];
            reinterpret_cast<uint32*>(outp + (size_t)R * 64)[lane] = v;
        }
    }
}

// ---------------- GCN aggregate ----------------
// WEIGHTED=true  (conv1): h[c] = relu(dinv[c]*(dinv[c]*g0[c] + sum dinv[s]*g0[s]) + b)
// WEIGHTED=false (conv2): h[c] = relu(dinv[c]*(pre[c] + sum pre[s]) + b), pre premultiplied
template <bool FUSE_HEAD, bool WEIGHTED>
__global__ __launch_bounds__(256) void k_agg(const float* __restrict__ bias,
                                             const float* __restrict__ Wl,
                                             const float* __restrict__ bl) {
    // agg1 runs strictly after the CSR/GEMM1 join -> safe to reset barrier counters
    if (WEIGHTED && blockIdx.x == 0 && threadIdx.x == 0) {
        #pragma unroll
        for (int j = 0; j < 8; j++) g_barc[j] = 0;
    }
    __shared__ float Wls[16 * 68];
    __shared__ float hs[8][64];
    __shared__ float blc[8];
    if (FUSE_HEAD) {
        for (int i = threadIdx.x; i < 16 * 64; i += 256) {
            int o = i & 15, k = i >> 4;
            int sel = o >> 3, oo = o & 7;
            Wls[o * 68 + k] = Wl[(sel * 64 + k) * 8 + oo];
        }
        if (threadIdx.x < 8) blc[threadIdx.x] = bl[threadIdx.x];
        __syncthreads();
    }

    int gw = (blockIdx.x * 256 + threadIdx.x) >> 5;   // grid exact: 12500 blocks
    int lane = threadIdx.x & 31;
    int w = threadIdx.x >> 5;
    float di = g_dinv[gw];
    int beg = g_rowptr[gw], end = g_rowptr[gw + 1];

    const __half2* hin = g_h0h;
    float2 hself = __half22float2(hin[(size_t)gw * 32 + lane]);
    float ax, ay;
    if (WEIGHTED) { ax = di * hself.x; ay = di * hself.y; }
    else          { ax = hself.x;      ay = hself.y; }

    int e = beg;
    for (; e + 4 <= end; e += 4) {
        int2 p0 = __ldg(&g_srcw[e]);
        int2 p1 = __ldg(&g_srcw[e + 1]);
        int2 p2 = __ldg(&g_srcw[e + 2]);
        int2 p3 = __ldg(&g_srcw[e + 3]);
        float2 v0 = __half22float2(__ldg(&hin[(size_t)p0.x * 32 + lane]));
        float2 v1 = __half22float2(__ldg(&hin[(size_t)p1.x * 32 + lane]));
        float2 v2 = __half22float2(__ldg(&hin[(size_t)p2.x * 32 + lane]));
        float2 v3 = __half22float2(__ldg(&hin[(size_t)p3.x * 32 + lane]));
        if (WEIGHTED) {
            float w0 = __int_as_float(p0.y), w1 = __int_as_float(p1.y);
            float w2 = __int_as_float(p2.y), w3 = __int_as_float(p3.y);
            ax += w0 * v0.x + w1 * v1.x + w2 * v2.x + w3 * v3.x;
            ay += w0 * v0.y + w1 * v1.y + w2 * v2.y + w3 * v3.y;
        } else {
            ax += v0.x + v1.x + v2.x + v3.x;
            ay += v0.y + v1.y + v2.y + v3.y;
        }
    }
    for (; e < end; e++) {
        int2 pp = __ldg(&g_srcw[e]);
        float2 v = __half22float2(__ldg(&hin[(size_t)pp.x * 32 + lane]));
        if (WEIGHTED) {
            float wv = __int_as_float(pp.y);
            ax += wv * v.x;
            ay += wv * v.y;
        } else {
            ax += v.x;
            ay += v.y;
        }
    }
    float2 b = reinterpret_cast<const float2*>(bias)[lane];
    float rx = fmaxf(fmaf(di, ax, b.x), 0.f);
    float ry = fmaxf(fmaf(di, ay, b.y), 0.f);

    if (!FUSE_HEAD) {
        g_h1h[(size_t)gw * 32 + lane] = __floats2half2_rn(rx, ry);
    } else {
        hs[w][2 * lane + 0] = rx;
        hs[w][2 * lane + 1] = ry;
        __syncwarp();
        if (lane < 16) {
            float acc = (lane < 8) ? blc[lane] : 0.f;
            const float4* h4 = reinterpret_cast<const float4*>(hs[w]);
            const float4* w4 = reinterpret_cast<const float4*>(Wls + lane * 68);
            #pragma unroll
            for (int k4 = 0; k4 < 16; k4++) {
                float4 hv = h4[k4];
                float4 wv = w4[k4];
                acc += hv.x * wv.x + hv.y * wv.y + hv.z * wv.z + hv.w * wv.w;
            }
            g_y[(size_t)gw * 16 + lane] = acc;
        }
        __syncwarp();
    }
}

// ---------------- edge phase: out[e] = y[row][0:8] + y[col][8:16] ----------------
__global__ void k_edge(const int* __restrict__ row, const int* __restrict__ col,
                       float* __restrict__ out) {
    int idx = blockIdx.x * 256 + threadIdx.x;
    if (idx >= NE * 2) return;
    int e = idx >> 1, c = idx & 1;
    int r = row[e], cl = col[e];
    const float4* y4 = reinterpret_cast<const float4*>(g_y);
    float4 a = y4[(size_t)r * 4 + c];
    float4 b = y4[(size_t)cl * 4 + 2 + c];
    float4 o;
    o.x = a.x + b.x; o.y = a.y + b.y; o.z = a.z + b.z; o.w = a.w + b.w;
    reinterpret_cast<float4*>(out)[idx] = o;
}

// ---------------- launch ----------------
extern "C" void kernel_launch(void* const* d_in, const int* in_sizes, int n_in,
                              void* d_out, int out_size) {
    const float* x  = (const float*)d_in[0];
    const int*   ei = (const int*)  d_in[1];
    const float* W1 = (const float*)d_in[2];
    const float* b1 = (const float*)d_in[3];
    const float* W2 = (const float*)d_in[4];
    const float* b2 = (const float*)d_in[5];
    const float* Wl = (const float*)d_in[6];
    const float* bl = (const float*)d_in[7];
    float* out = (float*)d_out;

    const int* row = ei;        // edge_index[0]
    const int* col = ei + NE;   // edge_index[1]

    const int GEMM_G = (NN + 63) / 64;   // 1563 blocks (64 rows each)

    // fork: GEMM1 (unscaled -> independent of CSR) overlaps k_csr
    cudaStream_t s2;
    cudaStreamCreateWithFlags(&s2, cudaStreamNonBlocking);
    cudaEvent_t evF, evJ;
    cudaEventCreateWithFlags(&evF, cudaEventDisableTiming);
    cudaEventCreateWithFlags(&evJ, cudaEventDisableTiming);

    cudaEventRecord(evF, 0);
    cudaStreamWaitEvent(s2, evF, 0);
    k_gemm_mma<FIN, false, false><<<GEMM_G, 128, 0, s2>>>(x, W1);  // conv1 GEMM (unscaled)
    cudaEventRecord(evJ, s2);

    k_csr<<<CSR_B, CSR_T>>>(row, col);                             // CSR (main stream)
    cudaStreamWaitEvent(0, evJ, 0);                                // join

    // conv1 agg (weighted; also resets g_barc)
    k_agg<false, true><<<(NN * 32) / 256, 256>>>(b1, Wl, bl);

    // conv2: premultiplied GEMM + unweighted agg with fused edge head
    k_gemm_mma<HID, true, true><<<GEMM_G, 128>>>(nullptr, W2);
    k_agg<true, false><<<(NN * 32) / 256, 256>>>(b2, Wl, bl);

    // per-edge sum
    k_edge<<<(NE * 2 + 255) / 256, 256>>>(row, col, out);

    cudaStreamDestroy(s2);
    cudaEventDestroy(evF);
    cudaEventDestroy(evJ);
}

// round 9
// speedup vs baseline: 1.5244x; 1.5244x over previous
#include <cuda_runtime.h>
#include <cuda_fp16.h>

#define NN 100000
#define NE 1600000
#define FIN 128
#define HID 64
#define SCAN_NBLK 98     // CSR-role blocks (also scan chunk count: ceil(NN/1024))
#define ALL_B 148
#define GEMM_BLKS (ALL_B - SCAN_NBLK)   // 50 GEMM-role blocks
#define NTILES ((NN + 63) / 64)         // 1563 GEMM1 tiles

typedef unsigned int uint32;

// ---------------- scratch (device globals; no allocation allowed) ----------------
__device__ __align__(256) __half2 g_h0h[(size_t)NN * 32];  // gemm out (fp16)
__device__ __align__(256) __half2 g_h1h[(size_t)NN * 32];  // conv1 hidden (fp16)
__device__ __align__(256) float  g_y [(size_t)NN * 16];    // per-node edge-head partials
__device__ __align__(256) float  g_dinv[NN];
__device__ __align__(256) int    g_deg[NN];
__device__ __align__(256) int    g_cursor[NN];
__device__ __align__(256) int    g_rowptr[NN + 1];
__device__ __align__(256) int2   g_srcw[NE];               // {src, bits(dinv[src])}
__device__ __align__(256) int    g_bsums[128];
__device__ int g_barc[8];   // one-shot barrier counters (zero-init; reset by agg1)

// ---------------- software grid barrier (CSR-role blocks only: target 98) ----------------
__device__ __forceinline__ void gbar(int j) {
    __syncthreads();
    if (threadIdx.x == 0) {
        __threadfence();
        atomicAdd(&g_barc[j], 1);
        volatile int* p = &g_barc[j];
        while (*p < SCAN_NBLK) { }
        __threadfence();
    }
    __syncthreads();
}

__device__ __forceinline__ void mma16816(float d[4], uint32 a0, uint32 a1, uint32 a2,
                                         uint32 a3, uint32 b0, uint32 b1) {
    asm volatile(
        "mma.sync.aligned.m16n8k16.row.col.f32.f16.f16.f32 "
        "{%0,%1,%2,%3}, {%4,%5,%6,%7}, {%8,%9}, {%0,%1,%2,%3};"
        : "+f"(d[0]), "+f"(d[1]), "+f"(d[2]), "+f"(d[3])
        : "r"(a0), "r"(a1), "r"(a2), "r"(a3), "r"(b0), "r"(b1));
}

// ============ fused kernel: blocks 0..97 build CSR, blocks 98..147 run GEMM1 ============
// GEMM1: g_h0h[r,:] = fp16(x[r,:] @ W1)   (unscaled -> no dependency on CSR/dinv)
// Dynamic smem (GEMM role): Wt[64][136] then Ahs[8*64][136]   (156,672 B)
extern __shared__ __half dsm_[];

__global__ __launch_bounds__(1024, 1) void k_csr_gemm(const int* __restrict__ row,
                                                      const int* __restrict__ col,
                                                      const float* __restrict__ x,
                                                      const float* __restrict__ W1) {
    const int tid = threadIdx.x, bid = blockIdx.x;

    if (bid >= SCAN_NBLK) {
        // ---------------- GEMM1 role ----------------
        __half (*Wt)[FIN + 8]  = reinterpret_cast<__half(*)[FIN + 8]>(dsm_);
        __half (*Ahs)[FIN + 8] = reinterpret_cast<__half(*)[FIN + 8]>(dsm_) + 64;

        for (int i = tid; i < FIN * 64; i += 1024) {
            int k = i >> 6, n = i & 63;
            Wt[n][k] = __float2half(W1[i]);
        }
        __syncthreads();

        const int g = tid >> 7;            // group 0..7 (128 threads each)
        const int t = tid & 127;
        const int warp = t >> 5, lane = t & 31;
        const int gr = lane >> 2;          // 0..7
        const int kc = (lane & 3) * 2;     // 0,2,4,6
        __half (*Ag)[FIN + 8] = Ahs + g * 64;
        const int barid = g + 1;           // named barriers 1..8

        for (int tile = (bid - SCAN_NBLK) * 8 + g; tile < NTILES; tile += GEMM_BLKS * 8) {
            const int rbase = tile * 64;
            // stage A tile (fp32 -> fp16), wide coalesced loads
            #pragma unroll
            for (int it = 0; it < 16; it++) {
                int i = it * 128 + t;
                int r = i >> 5, v = i & 31;
                int R = rbase + r;
                float4 f = make_float4(0.f, 0.f, 0.f, 0.f);
                if (R < NN) f = reinterpret_cast<const float4*>(x + (size_t)R * FIN)[v];
                __half2 h01 = __floats2half2_rn(f.x, f.y);
                __half2 h23 = __floats2half2_rn(f.z, f.w);
                uint2 pk = make_uint2(*reinterpret_cast<uint32*>(&h01),
                                      *reinterpret_cast<uint32*>(&h23));
                *reinterpret_cast<uint2*>(&Ag[r][v * 4]) = pk;
            }
            asm volatile("bar.sync %0, 128;" :: "r"(barid) : "memory");

            const int lr0 = warp * 16 + gr, lr1 = lr0 + 8;
            float d[8][4];
            #pragma unroll
            for (int nt = 0; nt < 8; nt++)
                #pragma unroll
                for (int q = 0; q < 4; q++) d[nt][q] = 0.f;

            #pragma unroll
            for (int q = 0; q < FIN / 16; q++) {
                int k0 = q * 16 + kc;
                uint32 a0 = *reinterpret_cast<const uint32*>(&Ag[lr0][k0]);
                uint32 a1 = *reinterpret_cast<const uint32*>(&Ag[lr1][k0]);
                uint32 a2 = *reinterpret_cast<const uint32*>(&Ag[lr0][k0 + 8]);
                uint32 a3 = *reinterpret_cast<const uint32*>(&Ag[lr1][k0 + 8]);
                #pragma unroll
                for (int nt = 0; nt < 8; nt++) {
                    int n = nt * 8 + gr;
                    uint32 b0 = *reinterpret_cast<const uint32*>(&Wt[n][k0]);
                    uint32 b1 = *reinterpret_cast<const uint32*>(&Wt[n][k0 + 8]);
                    mma16816(d[nt], a0, a1, a2, a3, b0, b1);
                }
            }

            // epilogue: fp16 into own-warp band of Ag, then coalesced row stores
            #pragma unroll
            for (int nt = 0; nt < 8; nt++) {
                int c = nt * 8 + kc;
                *reinterpret_cast<__half2*>(&Ag[lr0][c]) = __floats2half2_rn(d[nt][0], d[nt][1]);
                *reinterpret_cast<__half2*>(&Ag[lr1][c]) = __floats2half2_rn(d[nt][2], d[nt][3]);
            }
            __syncwarp();
            __half* outp = reinterpret_cast<__half*>(g_h0h);
            #pragma unroll
            for (int rr = 0; rr < 16; rr++) {
                int R = rbase + warp * 16 + rr;
                if (R < NN) {
                    uint32 v = reinterpret_cast<const uint32*>(&Ag[warp * 16 + rr][0])[lane];
                    reinterpret_cast<uint32*>(outp + (size_t)R * 64)[lane] = v;
                }
            }
            asm volatile("bar.sync %0, 128;" :: "r"(barid) : "memory");
        }
        return;
    }

    // ---------------- CSR role (blocks 0..97) ----------------
    const int gt = bid * 1024 + tid;
    const int gstride = SCAN_NBLK * 1024;

    for (int i = gt; i < NN; i += gstride) g_deg[i] = 0;
    gbar(0);

    for (int e = gt; e < NE; e += gstride) atomicAdd(&g_deg[col[e]], 1);
    gbar(1);

    int excl = 0;
    int valid = 0;
    {
        int i = bid * 1024 + tid;
        valid = (i < NN);
        int v = valid ? __ldcg(&g_deg[i]) : 0;
        if (valid) g_dinv[i] = rsqrtf((float)v + 1.0f);   // +1 self-loop
        int lane = tid & 31, wid = tid >> 5;
        int xs = v;
        #pragma unroll
        for (int dd = 1; dd < 32; dd <<= 1) {
            int y = __shfl_up_sync(0xffffffffu, xs, dd);
            if (lane >= dd) xs += y;
        }
        __shared__ int wsum[32];
        if (lane == 31) wsum[wid] = xs;
        __syncthreads();
        if (wid == 0) {
            int s = wsum[lane];
            int sx = s;
            #pragma unroll
            for (int dd = 1; dd < 32; dd <<= 1) {
                int y = __shfl_up_sync(0xffffffffu, sx, dd);
                if (lane >= dd) sx += y;
            }
            wsum[lane] = sx - s;
        }
        __syncthreads();
        int incl = xs + wsum[wid];
        excl = incl - v;
        if (tid == 1023) g_bsums[bid] = incl;
    }
    gbar(2);

    {
        __shared__ int ws[4];
        int v = 0, incl = 0;
        if (bid == 0) {
            if (tid < 128) {
                v = (tid < SCAN_NBLK) ? __ldcg(&g_bsums[tid]) : 0;
                int lane = tid & 31, wid = tid >> 5;
                int xs = v;
                #pragma unroll
                for (int dd = 1; dd < 32; dd <<= 1) {
                    int y = __shfl_up_sync(0xffffffffu, xs, dd);
                    if (lane >= dd) xs += y;
                }
                if (lane == 31) ws[wid] = xs;
                incl = xs;
            }
            __syncthreads();
            if (tid < 128) {
                int wid = tid >> 5;
                int off = 0;
                for (int w = 0; w < wid; w++) off += ws[w];
                incl += off;
                if (tid < SCAN_NBLK) g_bsums[tid] = incl - v;
            }
        }
    }
    gbar(3);

    if (valid) {
        int i = bid * 1024 + tid;
        int rp = excl + __ldcg(&g_bsums[bid]);
        g_rowptr[i] = rp;
        g_cursor[i] = rp;
    }
    if (bid == 0 && tid == 0) g_rowptr[NN] = NE;
    gbar(4);

    for (int e = gt; e < NE; e += gstride) {
        int c = col[e];
        int r = row[e];
        int p = atomicAdd(&g_cursor[c], 1);
        float dv = __ldcg(&g_dinv[r]);
        g_srcw[p] = make_int2(r, __float_as_int(dv));
    }
}

// ---------------- conv2 tensor-core GEMM (premultiplied, fp16 A from g_h1h) ----------------
__global__ __launch_bounds__(128) void k_gemm2(const float* __restrict__ W) {
    __shared__ __half Wt[64][HID + 8];
    __shared__ __half Ahs[64][HID + 8];

    for (int i = threadIdx.x; i < HID * 64; i += 128) {
        int k = i >> 6, n = i & 63;
        Wt[n][k] = __float2half(W[i]);
    }

    const int rbase = blockIdx.x * 64;
    const __half* Ah = reinterpret_cast<const __half*>(g_h1h);
    #pragma unroll
    for (int it = 0; it < 4; it++) {
        int i = it * 128 + threadIdx.x;
        int r = i >> 3, v = i & 7;
        int R = rbase + r;
        uint4 val = make_uint4(0, 0, 0, 0);
        if (R < NN) val = reinterpret_cast<const uint4*>(Ah + (size_t)R * HID)[v];
        reinterpret_cast<uint4*>(&Ahs[r][0])[v] = val;
    }
    __syncthreads();

    const int warp = threadIdx.x >> 5, lane = threadIdx.x & 31;
    const int gr = lane >> 2;
    const int kc = (lane & 3) * 2;
    const int lr0 = warp * 16 + gr, lr1 = lr0 + 8;
    const int R0 = rbase + lr0, R1 = rbase + lr1;

    float d[8][4];
    #pragma unroll
    for (int nt = 0; nt < 8; nt++)
        #pragma unroll
        for (int q = 0; q < 4; q++) d[nt][q] = 0.f;

    #pragma unroll
    for (int q = 0; q < HID / 16; q++) {
        int k0 = q * 16 + kc;
        uint32 a0 = *reinterpret_cast<const uint32*>(&Ahs[lr0][k0]);
        uint32 a1 = *reinterpret_cast<const uint32*>(&Ahs[lr1][k0]);
        uint32 a2 = *reinterpret_cast<const uint32*>(&Ahs[lr0][k0 + 8]);
        uint32 a3 = *reinterpret_cast<const uint32*>(&Ahs[lr1][k0 + 8]);
        #pragma unroll
        for (int nt = 0; nt < 8; nt++) {
            int n = nt * 8 + gr;
            uint32 b0 = *reinterpret_cast<const uint32*>(&Wt[n][k0]);
            uint32 b1 = *reinterpret_cast<const uint32*>(&Wt[n][k0 + 8]);
            mma16816(d[nt], a0, a1, a2, a3, b0, b1);
        }
    }

    float dv0 = (R0 < NN) ? g_dinv[R0] : 0.f;
    float dv1 = (R1 < NN) ? g_dinv[R1] : 0.f;
    #pragma unroll
    for (int nt = 0; nt < 8; nt++) {
        int c = nt * 8 + kc;
        *reinterpret_cast<__half2*>(&Ahs[lr0][c]) =
            __floats2half2_rn(d[nt][0] * dv0, d[nt][1] * dv0);
        *reinterpret_cast<__half2*>(&Ahs[lr1][c]) =
            __floats2half2_rn(d[nt][2] * dv1, d[nt][3] * dv1);
    }
    __syncwarp();
    __half* outp = reinterpret_cast<__half*>(g_h0h);
    #pragma unroll
    for (int rr = 0; rr < 16; rr++) {
        int R = rbase + warp * 16 + rr;
        if (R < NN) {
            uint32 v = reinterpret_cast<const uint32*>(&Ahs[warp * 16 + rr][0])[lane];
            reinterpret_cast<uint32*>(outp + (size_t)R * 64)[lane] = v;
        }
    }
}

// ---------------- GCN aggregate ----------------
// WEIGHTED=true  (conv1): h = relu(di*(di*g0[c] + sum dinv[s]*g0[s]) + b)
// WEIGHTED=false (conv2): h = relu(di*(pre[c] + sum pre[s]) + b)
template <bool FUSE_HEAD, bool WEIGHTED>
__global__ __launch_bounds__(256) void k_agg(const float* __restrict__ bias,
                                             const float* __restrict__ Wl,
                                             const float* __restrict__ bl) {
    if (WEIGHTED && blockIdx.x == 0 && threadIdx.x == 0) {
        #pragma unroll
        for (int j = 0; j < 8; j++) g_barc[j] = 0;   // reset for next replay
    }
    __shared__ float Wls[16 * 68];
    __shared__ float hs[8][64];
    __shared__ float blc[8];
    if (FUSE_HEAD) {
        for (int i = threadIdx.x; i < 16 * 64; i += 256) {
            int o = i & 15, k = i >> 4;
            int sel = o >> 3, oo = o & 7;
            Wls[o * 68 + k] = Wl[(sel * 64 + k) * 8 + oo];
        }
        if (threadIdx.x < 8) blc[threadIdx.x] = bl[threadIdx.x];
        __syncthreads();
    }

    int gw = (blockIdx.x * 256 + threadIdx.x) >> 5;
    int lane = threadIdx.x & 31;
    int w = threadIdx.x >> 5;
    float di = g_dinv[gw];
    int beg = g_rowptr[gw], end = g_rowptr[gw + 1];

    const __half2* hin = g_h0h;
    float2 hself = __half22float2(hin[(size_t)gw * 32 + lane]);
    float ax, ay;
    if (WEIGHTED) { ax = di * hself.x; ay = di * hself.y; }
    else          { ax = hself.x;      ay = hself.y; }

    int e = beg;
    for (; e + 4 <= end; e += 4) {
        int2 p0 = __ldg(&g_srcw[e]);
        int2 p1 = __ldg(&g_srcw[e + 1]);
        int2 p2 = __ldg(&g_srcw[e + 2]);
        int2 p3 = __ldg(&g_srcw[e + 3]);
        float2 v0 = __half22float2(__ldg(&hin[(size_t)p0.x * 32 + lane]));
        float2 v1 = __half22float2(__ldg(&hin[(size_t)p1.x * 32 + lane]));
        float2 v2 = __half22float2(__ldg(&hin[(size_t)p2.x * 32 + lane]));
        float2 v3 = __half22float2(__ldg(&hin[(size_t)p3.x * 32 + lane]));
        if (WEIGHTED) {
            float w0 = __int_as_float(p0.y), w1 = __int_as_float(p1.y);
            float w2 = __int_as_float(p2.y), w3 = __int_as_float(p3.y);
            ax += w0 * v0.x + w1 * v1.x + w2 * v2.x + w3 * v3.x;
            ay += w0 * v0.y + w1 * v1.y + w2 * v2.y + w3 * v3.y;
        } else {
            ax += v0.x + v1.x + v2.x + v3.x;
            ay += v0.y + v1.y + v2.y + v3.y;
        }
    }
    for (; e < end; e++) {
        int2 pp = __ldg(&g_srcw[e]);
        float2 v = __half22float2(__ldg(&hin[(size_t)pp.x * 32 + lane]));
        if (WEIGHTED) {
            float wv = __int_as_float(pp.y);
            ax += wv * v.x;
            ay += wv * v.y;
        } else {
            ax += v.x;
            ay += v.y;
        }
    }
    float2 b = reinterpret_cast<const float2*>(bias)[lane];
    float rx = fmaxf(fmaf(di, ax, b.x), 0.f);
    float ry = fmaxf(fmaf(di, ay, b.y), 0.f);

    if (!FUSE_HEAD) {
        g_h1h[(size_t)gw * 32 + lane] = __floats2half2_rn(rx, ry);
    } else {
        hs[w][2 * lane + 0] = rx;
        hs[w][2 * lane + 1] = ry;
        __syncwarp();
        if (lane < 16) {
            float acc = (lane < 8) ? blc[lane] : 0.f;
            const float4* h4 = reinterpret_cast<const float4*>(hs[w]);
            const float4* w4 = reinterpret_cast<const float4*>(Wls + lane * 68);
            #pragma unroll
            for (int k4 = 0; k4 < 16; k4++) {
                float4 hv = h4[k4];
                float4 wv = w4[k4];
                acc += hv.x * wv.x + hv.y * wv.y + hv.z * wv.z + hv.w * wv.w;
            }
            g_y[(size_t)gw * 16 + lane] = acc;
        }
        __syncwarp();
    }
}

// ---------------- edge phase: out[e] = y[row][0:8] + y[col][8:16] ----------------
__global__ void k_edge(const int* __restrict__ row, const int* __restrict__ col,
                       float* __restrict__ out) {
    int idx = blockIdx.x * 256 + threadIdx.x;
    if (idx >= NE * 2) return;
    int e = idx >> 1, c = idx & 1;
    int r = row[e], cl = col[e];
    const float4* y4 = reinterpret_cast<const float4*>(g_y);
    float4 a = y4[(size_t)r * 4 + c];
    float4 b = y4[(size_t)cl * 4 + 2 + c];
    float4 o;
    o.x = a.x + b.x; o.y = a.y + b.y; o.z = a.z + b.z; o.w = a.w + b.w;
    reinterpret_cast<float4*>(out)[idx] = o;
}

// ---------------- launch ----------------
extern "C" void kernel_launch(void* const* d_in, const int* in_sizes, int n_in,
                              void* d_out, int out_size) {
    const float* x  = (const float*)d_in[0];
    const int*   ei = (const int*)  d_in[1];
    const float* W1 = (const float*)d_in[2];
    const float* b1 = (const float*)d_in[3];
    const float* W2 = (const float*)d_in[4];
    const float* b2 = (const float*)d_in[5];
    const float* Wl = (const float*)d_in[6];
    const float* bl = (const float*)d_in[7];
    float* out = (float*)d_out;

    const int* row = ei;        // edge_index[0]
    const int* col = ei + NE;   // edge_index[1]

    // dynamic smem for the fused kernel: Wt (64 rows) + 8 group A tiles (512 rows), 136 halfs/row
    const int DSMEM = (64 + 8 * 64) * (FIN + 8) * (int)sizeof(__half);  // 156,672 B
    static bool attr_set = false;
    if (!attr_set) {
        cudaFuncSetAttribute(k_csr_gemm, cudaFuncAttributeMaxDynamicSharedMemorySize, DSMEM);
        attr_set = true;
    }

    // fused: CSR (blocks 0..97, spin barriers among themselves) + GEMM1 (blocks 98..147)
    k_csr_gemm<<<ALL_B, 1024, DSMEM>>>(row, col, x, W1);

    // conv1 agg (weighted; resets g_barc)
    k_agg<false, true><<<(NN * 32) / 256, 256>>>(b1, Wl, bl);

    // conv2: premultiplied GEMM + unweighted agg with fused edge head
    k_gemm2<<<NTILES, 128>>>(W2);
    k_agg<true, false><<<(NN * 32) / 256, 256>>>(b2, Wl, bl);

    // per-edge sum
    k_edge<<<(NE * 2 + 255) / 256, 256>>>(row, col, out);
}

// round 10
// speedup vs baseline: 1.8828x; 1.2351x over previous
#include <cuda_runtime.h>
#include <cuda_fp16.h>

#define NN 100000
#define NE 1600000
#define FIN 128
#define HID 64
#define SCAN_NBLK 98     // CSR-role blocks (also scan chunk count: ceil(NN/1024))
#define ALL_B 148
#define GEMM_BLKS (ALL_B - SCAN_NBLK)   // 50 GEMM-role blocks
#define NTILES ((NN + 63) / 64)         // 1563 64-row tiles

typedef unsigned int uint32;

// ---------------- scratch (device globals; no allocation allowed) ----------------
__device__ __align__(256) __half2 g_h0h[(size_t)NN * 32];  // gemm out (fp16)
__device__ __align__(256) __half2 g_h1h[(size_t)NN * 32];  // agg out (fp16; reused)
__device__ __align__(256) float  g_y [(size_t)NN * 16];    // per-node edge-head partials
__device__ __align__(256) float  g_dinv[NN];
__device__ __align__(256) int    g_deg[NN];
__device__ __align__(256) int    g_cursor[NN];
__device__ __align__(256) int    g_rowptr[NN + 1];
__device__ __align__(256) int2   g_srcw[NE];               // {src*32, bits(dinv[src])}
__device__ __align__(256) int    g_bsums[128];
__device__ int g_barc[8];   // one-shot barrier counters (zero-init; reset by agg1)

// ---------------- software grid barrier (CSR-role blocks only: target 98) ----------------
__device__ __forceinline__ void gbar(int j) {
    __syncthreads();
    if (threadIdx.x == 0) {
        __threadfence();
        atomicAdd(&g_barc[j], 1);
        volatile int* p = &g_barc[j];
        while (*p < SCAN_NBLK) { }
        __threadfence();
    }
    __syncthreads();
}

__device__ __forceinline__ void mma16816(float d[4], uint32 a0, uint32 a1, uint32 a2,
                                         uint32 a3, uint32 b0, uint32 b1) {
    asm volatile(
        "mma.sync.aligned.m16n8k16.row.col.f32.f16.f16.f32 "
        "{%0,%1,%2,%3}, {%4,%5,%6,%7}, {%8,%9}, {%0,%1,%2,%3};"
        : "+f"(d[0]), "+f"(d[1]), "+f"(d[2]), "+f"(d[3])
        : "r"(a0), "r"(a1), "r"(a2), "r"(a3), "r"(b0), "r"(b1));
}

// ============ fused kernel: blocks 0..97 build CSR, blocks 98..147 run GEMM1 ============
extern __shared__ __half dsm_[];

__global__ __launch_bounds__(1024, 1) void k_csr_gemm(const int* __restrict__ row,
                                                      const int* __restrict__ col,
                                                      const float* __restrict__ x,
                                                      const float* __restrict__ W1) {
    const int tid = threadIdx.x, bid = blockIdx.x;

    if (bid >= SCAN_NBLK) {
        // ---------------- GEMM1 role: g_h0h = fp16(x @ W1), unscaled ----------------
        __half (*Wt)[FIN + 8]  = reinterpret_cast<__half(*)[FIN + 8]>(dsm_);
        __half (*Ahs)[FIN + 8] = reinterpret_cast<__half(*)[FIN + 8]>(dsm_) + 64;

        for (int i = tid; i < FIN * 64; i += 1024) {
            int k = i >> 6, n = i & 63;
            Wt[n][k] = __float2half(W1[i]);
        }
        __syncthreads();

        const int g = tid >> 7;            // group 0..7 (128 threads each)
        const int t = tid & 127;
        const int warp = t >> 5, lane = t & 31;
        const int gr = lane >> 2;
        const int kc = (lane & 3) * 2;
        __half (*Ag)[FIN + 8] = Ahs + g * 64;
        const int barid = g + 1;

        for (int tile = (bid - SCAN_NBLK) * 8 + g; tile < NTILES; tile += GEMM_BLKS * 8) {
            const int rbase = tile * 64;
            #pragma unroll
            for (int it = 0; it < 16; it++) {
                int i = it * 128 + t;
                int r = i >> 5, v = i & 31;
                int R = rbase + r;
                float4 f = make_float4(0.f, 0.f, 0.f, 0.f);
                if (R < NN) f = reinterpret_cast<const float4*>(x + (size_t)R * FIN)[v];
                __half2 h01 = __floats2half2_rn(f.x, f.y);
                __half2 h23 = __floats2half2_rn(f.z, f.w);
                uint2 pk = make_uint2(*reinterpret_cast<uint32*>(&h01),
                                      *reinterpret_cast<uint32*>(&h23));
                *reinterpret_cast<uint2*>(&Ag[r][v * 4]) = pk;
            }
            asm volatile("bar.sync %0, 128;" :: "r"(barid) : "memory");

            const int lr0 = warp * 16 + gr, lr1 = lr0 + 8;
            float d[8][4];
            #pragma unroll
            for (int nt = 0; nt < 8; nt++)
                #pragma unroll
                for (int q = 0; q < 4; q++) d[nt][q] = 0.f;

            #pragma unroll
            for (int q = 0; q < FIN / 16; q++) {
                int k0 = q * 16 + kc;
                uint32 a0 = *reinterpret_cast<const uint32*>(&Ag[lr0][k0]);
                uint32 a1 = *reinterpret_cast<const uint32*>(&Ag[lr1][k0]);
                uint32 a2 = *reinterpret_cast<const uint32*>(&Ag[lr0][k0 + 8]);
                uint32 a3 = *reinterpret_cast<const uint32*>(&Ag[lr1][k0 + 8]);
                #pragma unroll
                for (int nt = 0; nt < 8; nt++) {
                    int n = nt * 8 + gr;
                    uint32 b0 = *reinterpret_cast<const uint32*>(&Wt[n][k0]);
                    uint32 b1 = *reinterpret_cast<const uint32*>(&Wt[n][k0 + 8]);
                    mma16816(d[nt], a0, a1, a2, a3, b0, b1);
                }
            }

            #pragma unroll
            for (int nt = 0; nt < 8; nt++) {
                int c = nt * 8 + kc;
                *reinterpret_cast<__half2*>(&Ag[lr0][c]) = __floats2half2_rn(d[nt][0], d[nt][1]);
                *reinterpret_cast<__half2*>(&Ag[lr1][c]) = __floats2half2_rn(d[nt][2], d[nt][3]);
            }
            __syncwarp();
            __half* outp = reinterpret_cast<__half*>(g_h0h);
            #pragma unroll
            for (int rr = 0; rr < 16; rr++) {
                int R = rbase + warp * 16 + rr;
                if (R < NN) {
                    uint32 v = reinterpret_cast<const uint32*>(&Ag[warp * 16 + rr][0])[lane];
                    reinterpret_cast<uint32*>(outp + (size_t)R * 64)[lane] = v;
                }
            }
            asm volatile("bar.sync %0, 128;" :: "r"(barid) : "memory");
        }
        return;
    }

    // ---------------- CSR role (blocks 0..97) ----------------
    const int gt = bid * 1024 + tid;
    const int gstride = SCAN_NBLK * 1024;

    for (int i = gt; i < NN; i += gstride) g_deg[i] = 0;
    gbar(0);

    for (int e = gt; e < NE; e += gstride) atomicAdd(&g_deg[col[e]], 1);
    gbar(1);

    int excl = 0;
    int valid = 0;
    {
        int i = bid * 1024 + tid;
        valid = (i < NN);
        int v = valid ? __ldcg(&g_deg[i]) : 0;
        if (valid) g_dinv[i] = rsqrtf((float)v + 1.0f);   // +1 self-loop
        int lane = tid & 31, wid = tid >> 5;
        int xs = v;
        #pragma unroll
        for (int dd = 1; dd < 32; dd <<= 1) {
            int y = __shfl_up_sync(0xffffffffu, xs, dd);
            if (lane >= dd) xs += y;
        }
        __shared__ int wsum[32];
        if (lane == 31) wsum[wid] = xs;
        __syncthreads();
        if (wid == 0) {
            int s = wsum[lane];
            int sx = s;
            #pragma unroll
            for (int dd = 1; dd < 32; dd <<= 1) {
                int y = __shfl_up_sync(0xffffffffu, sx, dd);
                if (lane >= dd) sx += y;
            }
            wsum[lane] = sx - s;
        }
        __syncthreads();
        int incl = xs + wsum[wid];
        excl = incl - v;
        if (tid == 1023) g_bsums[bid] = incl;
    }
    gbar(2);

    {
        __shared__ int ws[4];
        int v = 0, incl = 0;
        if (bid == 0) {
            if (tid < 128) {
                v = (tid < SCAN_NBLK) ? __ldcg(&g_bsums[tid]) : 0;
                int lane = tid & 31, wid = tid >> 5;
                int xs = v;
                #pragma unroll
                for (int dd = 1; dd < 32; dd <<= 1) {
                    int y = __shfl_up_sync(0xffffffffu, xs, dd);
                    if (lane >= dd) xs += y;
                }
                if (lane == 31) ws[wid] = xs;
                incl = xs;
            }
            __syncthreads();
            if (tid < 128) {
                int wid = tid >> 5;
                int off = 0;
                for (int w = 0; w < wid; w++) off += ws[w];
                incl += off;
                if (tid < SCAN_NBLK) g_bsums[tid] = incl - v;
            }
        }
    }
    gbar(3);

    if (valid) {
        int i = bid * 1024 + tid;
        int rp = excl + __ldcg(&g_bsums[bid]);
        g_rowptr[i] = rp;
        g_cursor[i] = rp;
    }
    if (bid == 0 && tid == 0) g_rowptr[NN] = NE;
    gbar(4);

    // payload: {src*32 (pre-scaled half2-row index), dinv[src]}
    for (int e = gt; e < NE; e += gstride) {
        int c = col[e];
        int r = row[e];
        int p = atomicAdd(&g_cursor[c], 1);
        float dv = __ldcg(&g_dinv[r]);
        g_srcw[p] = make_int2(r << 5, __float_as_int(dv));
    }
}

// ---------------- conv2 tensor-core GEMM (premultiplied, fp16 A from g_h1h) ----------------
__global__ __launch_bounds__(128) void k_gemm2(const float* __restrict__ W) {
    __shared__ __half Wt[64][HID + 8];
    __shared__ __half Ahs[64][HID + 8];

    for (int i = threadIdx.x; i < HID * 64; i += 128) {
        int k = i >> 6, n = i & 63;
        Wt[n][k] = __float2half(W[i]);
    }

    const int rbase = blockIdx.x * 64;
    const __half* Ah = reinterpret_cast<const __half*>(g_h1h);
    #pragma unroll
    for (int it = 0; it < 4; it++) {
        int i = it * 128 + threadIdx.x;
        int r = i >> 3, v = i & 7;
        int R = rbase + r;
        uint4 val = make_uint4(0, 0, 0, 0);
        if (R < NN) val = reinterpret_cast<const uint4*>(Ah + (size_t)R * HID)[v];
        reinterpret_cast<uint4*>(&Ahs[r][0])[v] = val;
    }
    __syncthreads();

    const int warp = threadIdx.x >> 5, lane = threadIdx.x & 31;
    const int gr = lane >> 2;
    const int kc = (lane & 3) * 2;
    const int lr0 = warp * 16 + gr, lr1 = lr0 + 8;
    const int R0 = rbase + lr0, R1 = rbase + lr1;

    float d[8][4];
    #pragma unroll
    for (int nt = 0; nt < 8; nt++)
        #pragma unroll
        for (int q = 0; q < 4; q++) d[nt][q] = 0.f;

    #pragma unroll
    for (int q = 0; q < HID / 16; q++) {
        int k0 = q * 16 + kc;
        uint32 a0 = *reinterpret_cast<const uint32*>(&Ahs[lr0][k0]);
        uint32 a1 = *reinterpret_cast<const uint32*>(&Ahs[lr1][k0]);
        uint32 a2 = *reinterpret_cast<const uint32*>(&Ahs[lr0][k0 + 8]);
        uint32 a3 = *reinterpret_cast<const uint32*>(&Ahs[lr1][k0 + 8]);
        #pragma unroll
        for (int nt = 0; nt < 8; nt++) {
            int n = nt * 8 + gr;
            uint32 b0 = *reinterpret_cast<const uint32*>(&Wt[n][k0]);
            uint32 b1 = *reinterpret_cast<const uint32*>(&Wt[n][k0 + 8]);
            mma16816(d[nt], a0, a1, a2, a3, b0, b1);
        }
    }

    float dv0 = (R0 < NN) ? g_dinv[R0] : 0.f;
    float dv1 = (R1 < NN) ? g_dinv[R1] : 0.f;
    #pragma unroll
    for (int nt = 0; nt < 8; nt++) {
        int c = nt * 8 + kc;
        *reinterpret_cast<__half2*>(&Ahs[lr0][c]) =
            __floats2half2_rn(d[nt][0] * dv0, d[nt][1] * dv0);
        *reinterpret_cast<__half2*>(&Ahs[lr1][c]) =
            __floats2half2_rn(d[nt][2] * dv1, d[nt][3] * dv1);
    }
    __syncwarp();
    __half* outp = reinterpret_cast<__half*>(g_h0h);
    #pragma unroll
    for (int rr = 0; rr < 16; rr++) {
        int R = rbase + warp * 16 + rr;
        if (R < NN) {
            uint32 v = reinterpret_cast<const uint32*>(&Ahs[warp * 16 + rr][0])[lane];
            reinterpret_cast<uint32*>(outp + (size_t)R * 64)[lane] = v;
        }
    }
}

// ---------------- GCN aggregate (both convs write fp16 to g_h1h) ----------------
// WEIGHTED=true  (conv1): h = relu(di*(di*g0[c] + sum dinv[s]*g0[s]) + b)
// WEIGHTED=false (conv2): h = relu(di*(pre[c] + sum pre[s]) + b)
template <bool WEIGHTED>
__global__ __launch_bounds__(256) void k_agg(const float* __restrict__ bias) {
    if (WEIGHTED && blockIdx.x == 0 && threadIdx.x == 0) {
        #pragma unroll
        for (int j = 0; j < 8; j++) g_barc[j] = 0;   // reset for next replay
    }
    int gw = (blockIdx.x * 256 + threadIdx.x) >> 5;
    int lane = threadIdx.x & 31;
    float di = g_dinv[gw];
    int beg = g_rowptr[gw], end = g_rowptr[gw + 1];

    const __half2* hin = g_h0h;
    float2 hself = __half22float2(hin[gw * 32 + lane]);
    float ax, ay;
    if (WEIGHTED) { ax = di * hself.x; ay = di * hself.y; }
    else          { ax = hself.x;      ay = hself.y; }

    int e = beg;
    for (; e + 4 <= end; e += 4) {
        int2 p0 = __ldg(&g_srcw[e]);
        int2 p1 = __ldg(&g_srcw[e + 1]);
        int2 p2 = __ldg(&g_srcw[e + 2]);
        int2 p3 = __ldg(&g_srcw[e + 3]);
        float2 v0 = __half22float2(__ldg(&hin[p0.x + lane]));
        float2 v1 = __half22float2(__ldg(&hin[p1.x + lane]));
        float2 v2 = __half22float2(__ldg(&hin[p2.x + lane]));
        float2 v3 = __half22float2(__ldg(&hin[p3.x + lane]));
        if (WEIGHTED) {
            float w0 = __int_as_float(p0.y), w1 = __int_as_float(p1.y);
            float w2 = __int_as_float(p2.y), w3 = __int_as_float(p3.y);
            ax += w0 * v0.x + w1 * v1.x + w2 * v2.x + w3 * v3.x;
            ay += w0 * v0.y + w1 * v1.y + w2 * v2.y + w3 * v3.y;
        } else {
            ax += v0.x + v1.x + v2.x + v3.x;
            ay += v0.y + v1.y + v2.y + v3.y;
        }
    }
    for (; e < end; e++) {
        int2 pp = __ldg(&g_srcw[e]);
        float2 v = __half22float2(__ldg(&hin[pp.x + lane]));
        if (WEIGHTED) {
            float wv = __int_as_float(pp.y);
            ax += wv * v.x;
            ay += wv * v.y;
        } else {
            ax += v.x;
            ay += v.y;
        }
    }
    float2 b = reinterpret_cast<const float2*>(bias)[lane];
    float rx = fmaxf(fmaf(di, ax, b.x), 0.f);
    float ry = fmaxf(fmaf(di, ay, b.y), 0.f);
    g_h1h[gw * 32 + lane] = __floats2half2_rn(rx, ry);
}

// ---------------- edge head GEMM: g_y[r,16] = h2[r,64] @ Wm[64,16] (+bl on cols 0..7) ----------------
__global__ __launch_bounds__(128) void k_head(const float* __restrict__ Wl,
                                              const float* __restrict__ bl) {
    __shared__ __half Wt[16][HID + 8];     // Wm transposed [o][k]
    __shared__ __half Ahs[64][HID + 8];

    for (int i = threadIdx.x; i < 16 * 64; i += 128) {
        int o = i >> 6, k = i & 63;
        float wv = (o < 8) ? Wl[k * 8 + o] : Wl[(64 + k) * 8 + (o - 8)];
        Wt[o][k] = __float2half(wv);
    }

    const int rbase = blockIdx.x * 64;
    const __half* Ah = reinterpret_cast<const __half*>(g_h1h);
    #pragma unroll
    for (int it = 0; it < 4; it++) {
        int i = it * 128 + threadIdx.x;
        int r = i >> 3, v = i & 7;
        int R = rbase + r;
        uint4 val = make_uint4(0, 0, 0, 0);
        if (R < NN) val = reinterpret_cast<const uint4*>(Ah + (size_t)R * HID)[v];
        reinterpret_cast<uint4*>(&Ahs[r][0])[v] = val;
    }
    __syncthreads();

    const int warp = threadIdx.x >> 5, lane = threadIdx.x & 31;
    const int gr = lane >> 2;
    const int kc = (lane & 3) * 2;
    const int lr0 = warp * 16 + gr, lr1 = lr0 + 8;
    const int R0 = rbase + lr0, R1 = rbase + lr1;

    float d[2][4];
    #pragma unroll
    for (int nt = 0; nt < 2; nt++)
        #pragma unroll
        for (int q = 0; q < 4; q++) d[nt][q] = 0.f;

    #pragma unroll
    for (int q = 0; q < HID / 16; q++) {
        int k0 = q * 16 + kc;
        uint32 a0 = *reinterpret_cast<const uint32*>(&Ahs[lr0][k0]);
        uint32 a1 = *reinterpret_cast<const uint32*>(&Ahs[lr1][k0]);
        uint32 a2 = *reinterpret_cast<const uint32*>(&Ahs[lr0][k0 + 8]);
        uint32 a3 = *reinterpret_cast<const uint32*>(&Ahs[lr1][k0 + 8]);
        #pragma unroll
        for (int nt = 0; nt < 2; nt++) {
            int n = nt * 8 + gr;
            uint32 b0 = *reinterpret_cast<const uint32*>(&Wt[n][k0]);
            uint32 b1 = *reinterpret_cast<const uint32*>(&Wt[n][k0 + 8]);
            mma16816(d[nt], a0, a1, a2, a3, b0, b1);
        }
    }

    float bx0 = __ldg(&bl[kc]), bx1 = __ldg(&bl[kc + 1]);
    if (R0 < NN) {
        *reinterpret_cast<float2*>(&g_y[(size_t)R0 * 16 + kc]) =
            make_float2(d[0][0] + bx0, d[0][1] + bx1);
        *reinterpret_cast<float2*>(&g_y[(size_t)R0 * 16 + 8 + kc]) =
            make_float2(d[1][0], d[1][1]);
    }
    if (R1 < NN) {
        *reinterpret_cast<float2*>(&g_y[(size_t)R1 * 16 + kc]) =
            make_float2(d[0][2] + bx0, d[0][3] + bx1);
        *reinterpret_cast<float2*>(&g_y[(size_t)R1 * 16 + 8 + kc]) =
            make_float2(d[1][2], d[1][3]);
    }
}

// ---------------- edge phase: out[e] = y[row][0:8] + y[col][8:16] ----------------
__global__ void k_edge(const int* __restrict__ row, const int* __restrict__ col,
                       float* __restrict__ out) {
    int idx = blockIdx.x * 256 + threadIdx.x;
    if (idx >= NE * 2) return;
    int e = idx >> 1, c = idx & 1;
    int r = row[e], cl = col[e];
    const float4* y4 = reinterpret_cast<const float4*>(g_y);
    float4 a = y4[(size_t)r * 4 + c];
    float4 b = y4[(size_t)cl * 4 + 2 + c];
    float4 o;
    o.x = a.x + b.x; o.y = a.y + b.y; o.z = a.z + b.z; o.w = a.w + b.w;
    reinterpret_cast<float4*>(out)[idx] = o;
}

// ---------------- launch ----------------
extern "C" void kernel_launch(void* const* d_in, const int* in_sizes, int n_in,
                              void* d_out, int out_size) {
    const float* x  = (const float*)d_in[0];
    const int*   ei = (const int*)  d_in[1];
    const float* W1 = (const float*)d_in[2];
    const float* b1 = (const float*)d_in[3];
    const float* W2 = (const float*)d_in[4];
    const float* b2 = (const float*)d_in[5];
    const float* Wl = (const float*)d_in[6];
    const float* bl = (const float*)d_in[7];
    float* out = (float*)d_out;

    const int* row = ei;        // edge_index[0]
    const int* col = ei + NE;   // edge_index[1]

    const int DSMEM = (64 + 8 * 64) * (FIN + 8) * (int)sizeof(__half);  // 156,672 B
    static bool attr_set = false;
    if (!attr_set) {
        cudaFuncSetAttribute(k_csr_gemm, cudaFuncAttributeMaxDynamicSharedMemorySize, DSMEM);
        attr_set = true;
    }

    // fused: CSR (blocks 0..97) + GEMM1 (blocks 98..147)
    k_csr_gemm<<<ALL_B, 1024, DSMEM>>>(row, col, x, W1);

    // conv1 agg (weighted; resets g_barc) -> h1h
    k_agg<true><<<(NN * 32) / 256, 256>>>(b1);

    // conv2: premultiplied GEMM (h1h -> h0h) + unweighted agg (-> h1h)
    k_gemm2<<<NTILES, 128>>>(W2);
    k_agg<false><<<(NN * 32) / 256, 256>>>(b2);

    // edge head GEMM (h1h -> y), then per-edge sum
    k_head<<<NTILES, 128>>>(Wl, bl);
    k_edge<<<(NE * 2 + 255) / 256, 256>>>(row, col, out);
}

// round 11
// speedup vs baseline: 1.9396x; 1.0302x over previous
#include <cuda_runtime.h>
#include <cuda_fp16.h>

#define NN 100000
#define NE 1600000
#define FIN 128
#define HID 64
#define SCAN_NBLK 98     // CSR-role blocks (also scan chunk count: ceil(NN/1024))
#define ALL_B 148
#define GEMM_BLKS (ALL_B - SCAN_NBLK)   // 50 GEMM-role blocks
#define NTILES ((NN + 63) / 64)         // 1563 64-row tiles

typedef unsigned int uint32;

// ---------------- scratch (device globals; no allocation allowed) ----------------
__device__ __align__(256) __half2 g_h0h[(size_t)NN * 32];  // gemm out (fp16)
__device__ __align__(256) __half2 g_h1h[(size_t)NN * 32];  // agg out (fp16; reused)
__device__ __align__(256) float  g_y [(size_t)NN * 16];    // per-node edge-head partials
__device__ __align__(256) float  g_dinv[NN];
__device__ __align__(256) int    g_deg[NN];
__device__ __align__(256) int    g_rank[NE];               // per-edge rank within dest
__device__ __align__(256) int    g_rowptr[NN + 1];
__device__ __align__(256) int2   g_srcw[NE];               // {src*32, bits(dinv[src])}
__device__ __align__(256) int    g_bsums[128];
__device__ int g_barc[8];   // one-shot barrier counters (zero-init; reset by agg1)

// ---------------- software grid barrier (CSR-role blocks only: target 98) ----------------
__device__ __forceinline__ void gbar(int j) {
    __syncthreads();
    if (threadIdx.x == 0) {
        __threadfence();
        atomicAdd(&g_barc[j], 1);
        volatile int* p = &g_barc[j];
        while (*p < SCAN_NBLK) { }
        __threadfence();
    }
    __syncthreads();
}

__device__ __forceinline__ void mma16816(float d[4], uint32 a0, uint32 a1, uint32 a2,
                                         uint32 a3, uint32 b0, uint32 b1) {
    asm volatile(
        "mma.sync.aligned.m16n8k16.row.col.f32.f16.f16.f32 "
        "{%0,%1,%2,%3}, {%4,%5,%6,%7}, {%8,%9}, {%0,%1,%2,%3};"
        : "+f"(d[0]), "+f"(d[1]), "+f"(d[2]), "+f"(d[3])
        : "r"(a0), "r"(a1), "r"(a2), "r"(a3), "r"(b0), "r"(b1));
}

// ============ fused kernel: blocks 0..97 build CSR, blocks 98..147 run GEMM1 ============
extern __shared__ __half dsm_[];

__global__ __launch_bounds__(1024, 1) void k_csr_gemm(const int* __restrict__ row,
                                                      const int* __restrict__ col,
                                                      const float* __restrict__ x,
                                                      const float* __restrict__ W1) {
    const int tid = threadIdx.x, bid = blockIdx.x;

    if (bid >= SCAN_NBLK) {
        // ---------------- GEMM1 role: g_h0h = fp16(x @ W1), unscaled ----------------
        __half (*Wt)[FIN + 8]  = reinterpret_cast<__half(*)[FIN + 8]>(dsm_);
        __half (*Ahs)[FIN + 8] = reinterpret_cast<__half(*)[FIN + 8]>(dsm_) + 64;

        for (int i = tid; i < FIN * 64; i += 1024) {
            int k = i >> 6, n = i & 63;
            Wt[n][k] = __float2half(W1[i]);
        }
        __syncthreads();

        const int g = tid >> 7;            // group 0..7 (128 threads each)
        const int t = tid & 127;
        const int warp = t >> 5, lane = t & 31;
        const int gr = lane >> 2;
        const int kc = (lane & 3) * 2;
        __half (*Ag)[FIN + 8] = Ahs + g * 64;
        const int barid = g + 1;

        for (int tile = (bid - SCAN_NBLK) * 8 + g; tile < NTILES; tile += GEMM_BLKS * 8) {
            const int rbase = tile * 64;
            #pragma unroll
            for (int it = 0; it < 16; it++) {
                int i = it * 128 + t;
                int r = i >> 5, v = i & 31;
                int R = rbase + r;
                float4 f = make_float4(0.f, 0.f, 0.f, 0.f);
                if (R < NN) f = reinterpret_cast<const float4*>(x + (size_t)R * FIN)[v];
                __half2 h01 = __floats2half2_rn(f.x, f.y);
                __half2 h23 = __floats2half2_rn(f.z, f.w);
                uint2 pk = make_uint2(*reinterpret_cast<uint32*>(&h01),
                                      *reinterpret_cast<uint32*>(&h23));
                *reinterpret_cast<uint2*>(&Ag[r][v * 4]) = pk;
            }
            asm volatile("bar.sync %0, 128;" :: "r"(barid) : "memory");

            const int lr0 = warp * 16 + gr, lr1 = lr0 + 8;
            float d[8][4];
            #pragma unroll
            for (int nt = 0; nt < 8; nt++)
                #pragma unroll
                for (int q = 0; q < 4; q++) d[nt][q] = 0.f;

            #pragma unroll
            for (int q = 0; q < FIN / 16; q++) {
                int k0 = q * 16 + kc;
                uint32 a0 = *reinterpret_cast<const uint32*>(&Ag[lr0][k0]);
                uint32 a1 = *reinterpret_cast<const uint32*>(&Ag[lr1][k0]);
                uint32 a2 = *reinterpret_cast<const uint32*>(&Ag[lr0][k0 + 8]);
                uint32 a3 = *reinterpret_cast<const uint32*>(&Ag[lr1][k0 + 8]);
                #pragma unroll
                for (int nt = 0; nt < 8; nt++) {
                    int n = nt * 8 + gr;
                    uint32 b0 = *reinterpret_cast<const uint32*>(&Wt[n][k0]);
                    uint32 b1 = *reinterpret_cast<const uint32*>(&Wt[n][k0 + 8]);
                    mma16816(d[nt], a0, a1, a2, a3, b0, b1);
                }
            }

            #pragma unroll
            for (int nt = 0; nt < 8; nt++) {
                int c = nt * 8 + kc;
                *reinterpret_cast<__half2*>(&Ag[lr0][c]) = __floats2half2_rn(d[nt][0], d[nt][1]);
                *reinterpret_cast<__half2*>(&Ag[lr1][c]) = __floats2half2_rn(d[nt][2], d[nt][3]);
            }
            __syncwarp();
            __half* outp = reinterpret_cast<__half*>(g_h0h);
            #pragma unroll
            for (int rr = 0; rr < 16; rr++) {
                int R = rbase + warp * 16 + rr;
                if (R < NN) {
                    uint32 v = reinterpret_cast<const uint32*>(&Ag[warp * 16 + rr][0])[lane];
                    reinterpret_cast<uint32*>(outp + (size_t)R * 64)[lane] = v;
                }
            }
            asm volatile("bar.sync %0, 128;" :: "r"(barid) : "memory");
        }
        return;
    }

    // ---------------- CSR role (blocks 0..97) ----------------
    const int gt = bid * 1024 + tid;
    const int gstride = SCAN_NBLK * 1024;

    for (int i = gt; i < NN; i += gstride) g_deg[i] = 0;
    gbar(0);

    // histogram + per-edge rank (atomic returns placement within destination bucket)
    for (int e = gt; e < NE; e += gstride) g_rank[e] = atomicAdd(&g_deg[col[e]], 1);
    gbar(1);

    int excl = 0;
    int valid = 0;
    {
        int i = bid * 1024 + tid;
        valid = (i < NN);
        int v = valid ? __ldcg(&g_deg[i]) : 0;
        if (valid) g_dinv[i] = rsqrtf((float)v + 1.0f);   // +1 self-loop
        int lane = tid & 31, wid = tid >> 5;
        int xs = v;
        #pragma unroll
        for (int dd = 1; dd < 32; dd <<= 1) {
            int y = __shfl_up_sync(0xffffffffu, xs, dd);
            if (lane >= dd) xs += y;
        }
        __shared__ int wsum[32];
        if (lane == 31) wsum[wid] = xs;
        __syncthreads();
        if (wid == 0) {
            int s = wsum[lane];
            int sx = s;
            #pragma unroll
            for (int dd = 1; dd < 32; dd <<= 1) {
                int y = __shfl_up_sync(0xffffffffu, sx, dd);
                if (lane >= dd) sx += y;
            }
            wsum[lane] = sx - s;
        }
        __syncthreads();
        int incl = xs + wsum[wid];
        excl = incl - v;
        if (tid == 1023) g_bsums[bid] = incl;
    }
    gbar(2);

    {
        __shared__ int ws[4];
        int v = 0, incl = 0;
        if (bid == 0) {
            if (tid < 128) {
                v = (tid < SCAN_NBLK) ? __ldcg(&g_bsums[tid]) : 0;
                int lane = tid & 31, wid = tid >> 5;
                int xs = v;
                #pragma unroll
                for (int dd = 1; dd < 32; dd <<= 1) {
                    int y = __shfl_up_sync(0xffffffffu, xs, dd);
                    if (lane >= dd) xs += y;
                }
                if (lane == 31) ws[wid] = xs;
                incl = xs;
            }
            __syncthreads();
            if (tid < 128) {
                int wid = tid >> 5;
                int off = 0;
                for (int w = 0; w < wid; w++) off += ws[w];
                incl += off;
                if (tid < SCAN_NBLK) g_bsums[tid] = incl - v;
            }
        }
    }
    gbar(3);

    if (valid) {
        int i = bid * 1024 + tid;
        g_rowptr[i] = excl + __ldcg(&g_bsums[bid]);
    }
    if (bid == 0 && tid == 0) g_rowptr[NN] = NE;
    gbar(4);

    // fill (atomic-free): p = rowptr[col[e]] + rank[e]
    for (int e = gt; e < NE; e += gstride) {
        int c = col[e];
        int r = row[e];
        int p = __ldcg(&g_rowptr[c]) + __ldcg(&g_rank[e]);
        float dv = __ldcg(&g_dinv[r]);
        g_srcw[p] = make_int2(r << 5, __float_as_int(dv));
    }
}

// ---------------- conv2 tensor-core GEMM (premultiplied, fp16 A from g_h1h) ----------------
__global__ __launch_bounds__(128) void k_gemm2(const float* __restrict__ W) {
    __shared__ __half Wt[64][HID + 8];
    __shared__ __half Ahs[64][HID + 8];

    for (int i = threadIdx.x; i < HID * 64; i += 128) {
        int k = i >> 6, n = i & 63;
        Wt[n][k] = __float2half(W[i]);
    }

    const int rbase = blockIdx.x * 64;
    const __half* Ah = reinterpret_cast<const __half*>(g_h1h);
    #pragma unroll
    for (int it = 0; it < 4; it++) {
        int i = it * 128 + threadIdx.x;
        int r = i >> 3, v = i & 7;
        int R = rbase + r;
        uint4 val = make_uint4(0, 0, 0, 0);
        if (R < NN) val = reinterpret_cast<const uint4*>(Ah + (size_t)R * HID)[v];
        reinterpret_cast<uint4*>(&Ahs[r][0])[v] = val;
    }
    __syncthreads();

    const int warp = threadIdx.x >> 5, lane = threadIdx.x & 31;
    const int gr = lane >> 2;
    const int kc = (lane & 3) * 2;
    const int lr0 = warp * 16 + gr, lr1 = lr0 + 8;
    const int R0 = rbase + lr0, R1 = rbase + lr1;

    float d[8][4];
    #pragma unroll
    for (int nt = 0; nt < 8; nt++)
        #pragma unroll
        for (int q = 0; q < 4; q++) d[nt][q] = 0.f;

    #pragma unroll
    for (int q = 0; q < HID / 16; q++) {
        int k0 = q * 16 + kc;
        uint32 a0 = *reinterpret_cast<const uint32*>(&Ahs[lr0][k0]);
        uint32 a1 = *reinterpret_cast<const uint32*>(&Ahs[lr1][k0]);
        uint32 a2 = *reinterpret_cast<const uint32*>(&Ahs[lr0][k0 + 8]);
        uint32 a3 = *reinterpret_cast<const uint32*>(&Ahs[lr1][k0 + 8]);
        #pragma unroll
        for (int nt = 0; nt < 8; nt++) {
            int n = nt * 8 + gr;
            uint32 b0 = *reinterpret_cast<const uint32*>(&Wt[n][k0]);
            uint32 b1 = *reinterpret_cast<const uint32*>(&Wt[n][k0 + 8]);
            mma16816(d[nt], a0, a1, a2, a3, b0, b1);
        }
    }

    float dv0 = (R0 < NN) ? g_dinv[R0] : 0.f;
    float dv1 = (R1 < NN) ? g_dinv[R1] : 0.f;
    #pragma unroll
    for (int nt = 0; nt < 8; nt++) {
        int c = nt * 8 + kc;
        *reinterpret_cast<__half2*>(&Ahs[lr0][c]) =
            __floats2half2_rn(d[nt][0] * dv0, d[nt][1] * dv0);
        *reinterpret_cast<__half2*>(&Ahs[lr1][c]) =
            __floats2half2_rn(d[nt][2] * dv1, d[nt][3] * dv1);
    }
    __syncwarp();
    __half* outp = reinterpret_cast<__half*>(g_h0h);
    #pragma unroll
    for (int rr = 0; rr < 16; rr++) {
        int R = rbase + warp * 16 + rr;
        if (R < NN) {
            uint32 v = reinterpret_cast<const uint32*>(&Ahs[warp * 16 + rr][0])[lane];
            reinterpret_cast<uint32*>(outp + (size_t)R * 64)[lane] = v;
        }
    }
}

// ---------------- GCN aggregate (both convs write fp16 to g_h1h) ----------------
// WEIGHTED=true  (conv1): h = relu(di*(di*g0[c] + sum dinv[s]*g0[s]) + b)
// WEIGHTED=false (conv2): h = relu(di*(pre[c] + sum pre[s]) + b)
template <bool WEIGHTED>
__global__ __launch_bounds__(256) void k_agg(const float* __restrict__ bias) {
    if (WEIGHTED && blockIdx.x == 0 && threadIdx.x == 0) {
        #pragma unroll
        for (int j = 0; j < 8; j++) g_barc[j] = 0;   // reset for next replay
    }
    int gw = (blockIdx.x * 256 + threadIdx.x) >> 5;
    int lane = threadIdx.x & 31;
    float di = g_dinv[gw];
    int beg = g_rowptr[gw], end = g_rowptr[gw + 1];

    const __half2* hin = g_h0h;
    float2 hself = __half22float2(hin[gw * 32 + lane]);
    float ax, ay;
    if (WEIGHTED) { ax = di * hself.x; ay = di * hself.y; }
    else          { ax = hself.x;      ay = hself.y; }

    int e = beg;
    // unroll-8 main loop: 8 outstanding gathers per warp for latency hiding
    for (; e + 8 <= end; e += 8) {
        int2 p[8];
        #pragma unroll
        for (int u = 0; u < 8; u++) p[u] = __ldg(&g_srcw[e + u]);
        float2 v[8];
        #pragma unroll
        for (int u = 0; u < 8; u++) v[u] = __half22float2(__ldg(&hin[p[u].x + lane]));
        #pragma unroll
        for (int u = 0; u < 8; u++) {
            if (WEIGHTED) {
                float wv = __int_as_float(p[u].y);
                ax += wv * v[u].x;
                ay += wv * v[u].y;
            } else {
                ax += v[u].x;
                ay += v[u].y;
            }
        }
    }
    for (; e + 2 <= end; e += 2) {
        int2 p0 = __ldg(&g_srcw[e]);
        int2 p1 = __ldg(&g_srcw[e + 1]);
        float2 v0 = __half22float2(__ldg(&hin[p0.x + lane]));
        float2 v1 = __half22float2(__ldg(&hin[p1.x + lane]));
        if (WEIGHTED) {
            float w0 = __int_as_float(p0.y), w1 = __int_as_float(p1.y);
            ax += w0 * v0.x + w1 * v1.x;
            ay += w0 * v0.y + w1 * v1.y;
        } else {
            ax += v0.x + v1.x;
            ay += v0.y + v1.y;
        }
    }
    if (e < end) {
        int2 pp = __ldg(&g_srcw[e]);
        float2 v = __half22float2(__ldg(&hin[pp.x + lane]));
        if (WEIGHTED) {
            float wv = __int_as_float(pp.y);
            ax += wv * v.x;
            ay += wv * v.y;
        } else {
            ax += v.x;
            ay += v.y;
        }
    }
    float2 b = reinterpret_cast<const float2*>(bias)[lane];
    float rx = fmaxf(fmaf(di, ax, b.x), 0.f);
    float ry = fmaxf(fmaf(di, ay, b.y), 0.f);
    g_h1h[gw * 32 + lane] = __floats2half2_rn(rx, ry);
}

// ---------------- edge head GEMM: g_y[r,16] = h2[r,64] @ Wm[64,16] (+bl on cols 0..7) ----------------
__global__ __launch_bounds__(128) void k_head(const float* __restrict__ Wl,
                                              const float* __restrict__ bl) {
    __shared__ __half Wt[16][HID + 8];     // Wm transposed [o][k]
    __shared__ __half Ahs[64][HID + 8];

    for (int i = threadIdx.x; i < 16 * 64; i += 128) {
        int o = i >> 6, k = i & 63;
        float wv = (o < 8) ? Wl[k * 8 + o] : Wl[(64 + k) * 8 + (o - 8)];
        Wt[o][k] = __float2half(wv);
    }

    const int rbase = blockIdx.x * 64;
    const __half* Ah = reinterpret_cast<const __half*>(g_h1h);
    #pragma unroll
    for (int it = 0; it < 4; it++) {
        int i = it * 128 + threadIdx.x;
        int r = i >> 3, v = i & 7;
        int R = rbase + r;
        uint4 val = make_uint4(0, 0, 0, 0);
        if (R < NN) val = reinterpret_cast<const uint4*>(Ah + (size_t)R * HID)[v];
        reinterpret_cast<uint4*>(&Ahs[r][0])[v] = val;
    }
    __syncthreads();

    const int warp = threadIdx.x >> 5, lane = threadIdx.x & 31;
    const int gr = lane >> 2;
    const int kc = (lane & 3) * 2;
    const int lr0 = warp * 16 + gr, lr1 = lr0 + 8;
    const int R0 = rbase + lr0, R1 = rbase + lr1;

    float d[2][4];
    #pragma unroll
    for (int nt = 0; nt < 2; nt++)
        #pragma unroll
        for (int q = 0; q < 4; q++) d[nt][q] = 0.f;

    #pragma unroll
    for (int q = 0; q < HID / 16; q++) {
        int k0 = q * 16 + kc;
        uint32 a0 = *reinterpret_cast<const uint32*>(&Ahs[lr0][k0]);
        uint32 a1 = *reinterpret_cast<const uint32*>(&Ahs[lr1][k0]);
        uint32 a2 = *reinterpret_cast<const uint32*>(&Ahs[lr0][k0 + 8]);
        uint32 a3 = *reinterpret_cast<const uint32*>(&Ahs[lr1][k0 + 8]);
        #pragma unroll
        for (int nt = 0; nt < 2; nt++) {
            int n = nt * 8 + gr;
            uint32 b0 = *reinterpret_cast<const uint32*>(&Wt[n][k0]);
            uint32 b1 = *reinterpret_cast<const uint32*>(&Wt[n][k0 + 8]);
            mma16816(d[nt], a0, a1, a2, a3, b0, b1);
        }
    }

    float bx0 = __ldg(&bl[kc]), bx1 = __ldg(&bl[kc + 1]);
    if (R0 < NN) {
        *reinterpret_cast<float2*>(&g_y[(size_t)R0 * 16 + kc]) =
            make_float2(d[0][0] + bx0, d[0][1] + bx1);
        *reinterpret_cast<float2*>(&g_y[(size_t)R0 * 16 + 8 + kc]) =
            make_float2(d[1][0], d[1][1]);
    }
    if (R1 < NN) {
        *reinterpret_cast<float2*>(&g_y[(size_t)R1 * 16 + kc]) =
            make_float2(d[0][2] + bx0, d[0][3] + bx1);
        *reinterpret_cast<float2*>(&g_y[(size_t)R1 * 16 + 8 + kc]) =
            make_float2(d[1][2], d[1][3]);
    }
}

// ---------------- edge phase: out[e] = y[row][0:8] + y[col][8:16] ----------------
__global__ void k_edge(const int* __restrict__ row, const int* __restrict__ col,
                       float* __restrict__ out) {
    int idx = blockIdx.x * 256 + threadIdx.x;
    if (idx >= NE * 2) return;
    int e = idx >> 1, c = idx & 1;
    int r = row[e], cl = col[e];
    const float4* y4 = reinterpret_cast<const float4*>(g_y);
    float4 a = y4[(size_t)r * 4 + c];
    float4 b = y4[(size_t)cl * 4 + 2 + c];
    float4 o;
    o.x = a.x + b.x; o.y = a.y + b.y; o.z = a.z + b.z; o.w = a.w + b.w;
    reinterpret_cast<float4*>(out)[idx] = o;
}

// ---------------- launch ----------------
extern "C" void kernel_launch(void* const* d_in, const int* in_sizes, int n_in,
                              void* d_out, int out_size) {
    const float* x  = (const float*)d_in[0];
    const int*   ei = (const int*)  d_in[1];
    const float* W1 = (const float*)d_in[2];
    const float* b1 = (const float*)d_in[3];
    const float* W2 = (const float*)d_in[4];
    const float* b2 = (const float*)d_in[5];
    const float* Wl = (const float*)d_in[6];
    const float* bl = (const float*)d_in[7];
    float* out = (float*)d_out;

    const int* row = ei;        // edge_index[0]
    const int* col = ei + NE;   // edge_index[1]

    const int DSMEM = (64 + 8 * 64) * (FIN + 8) * (int)sizeof(__half);  // 156,672 B
    static bool attr_set = false;
    if (!attr_set) {
        cudaFuncSetAttribute(k_csr_gemm, cudaFuncAttributeMaxDynamicSharedMemorySize, DSMEM);
        attr_set = true;
    }

    // fused: CSR (blocks 0..97) + GEMM1 (blocks 98..147)
    k_csr_gemm<<<ALL_B, 1024, DSMEM>>>(row, col, x, W1);

    // conv1 agg (weighted; resets g_barc) -> h1h
    k_agg<true><<<(NN * 32) / 256, 256>>>(b1);

    // conv2: premultiplied GEMM (h1h -> h0h) + unweighted agg (-> h1h)
    k_gemm2<<<NTILES, 128>>>(W2);
    k_agg<false><<<(NN * 32) / 256, 256>>>(b2);

    // edge head GEMM (h1h -> y), then per-edge sum
    k_head<<<NTILES, 128>>>(Wl, bl);
    k_edge<<<(NE * 2 + 255) / 256, 256>>>(row, col, out);
}

// round 12
// speedup vs baseline: 2.0547x; 1.0593x over previous
#include <cuda_runtime.h>
#include <cuda_fp16.h>

#define NN 100000
#define NE 1600000
#define FIN 128
#define HID 64
#define SCAN_NBLK 98     // CSR-role blocks (scan chunk count: ceil(NN/1024))
#define ALL_B 148
#define GEMM_BLKS (ALL_B - SCAN_NBLK)   // 50 GEMM-role blocks
#define NTILES ((NN + 63) / 64)         // 1563 64-row tiles

typedef unsigned int uint32;

// ---------------- scratch (device globals; no allocation allowed) ----------------
__device__ __align__(256) __half2 g_h0h[(size_t)NN * 32];  // gemm out (fp16, premultiplied)
__device__ __align__(256) __half2 g_h1h[(size_t)NN * 32];  // agg out (fp16; reused)
__device__ __align__(256) float  g_y [(size_t)NN * 16];    // per-node edge-head partials
__device__ __align__(256) float  g_dinv[NN];
__device__ __align__(256) int    g_deg[NN];                // zeroed by k_edge for next replay
__device__ __align__(256) int    g_rank[NE];               // per-edge rank within dest
__device__ __align__(256) int    g_rowptr[NN + 1];
__device__ __align__(256) int    g_src[NE];                // payload: src*32 (pre-scaled)
__device__ __align__(256) int    g_bsums[128];
__device__ int g_barc[8];   // one-shot barrier counters (zeroed by k_edge)

// ---------------- software grid barrier (CSR-role blocks only: target 98) ----------------
__device__ __forceinline__ void gbar(int j) {
    __syncthreads();
    if (threadIdx.x == 0) {
        __threadfence();
        atomicAdd(&g_barc[j], 1);
        volatile int* p = &g_barc[j];
        while (*p < SCAN_NBLK) { }
        __threadfence();
    }
    __syncthreads();
}

__device__ __forceinline__ void mma16816(float d[4], uint32 a0, uint32 a1, uint32 a2,
                                         uint32 a3, uint32 b0, uint32 b1) {
    asm volatile(
        "mma.sync.aligned.m16n8k16.row.col.f32.f16.f16.f32 "
        "{%0,%1,%2,%3}, {%4,%5,%6,%7}, {%8,%9}, {%0,%1,%2,%3};"
        : "+f"(d[0]), "+f"(d[1]), "+f"(d[2]), "+f"(d[3])
        : "r"(a0), "r"(a1), "r"(a2), "r"(a3), "r"(b0), "r"(b1));
}

// ---------------- histogram + rank (full chip; deg must be zero on entry) ----------------
__global__ __launch_bounds__(1024) void k_hist(const int* __restrict__ col) {
    int gt = blockIdx.x * 1024 + threadIdx.x;
    for (int e = gt; e < NE; e += ALL_B * 1024)
        g_rank[e] = atomicAdd(&g_deg[col[e]], 1);
}

// ============ fused: blocks 0..97 scan+fill, blocks 98..147 premultiplied GEMM1 ============
extern __shared__ __half dsm_[];

__global__ __launch_bounds__(1024, 1) void k_scan_gemm(const int* __restrict__ row,
                                                       const int* __restrict__ col,
                                                       const float* __restrict__ x,
                                                       const float* __restrict__ W1) {
    const int tid = threadIdx.x, bid = blockIdx.x;

    if (bid >= SCAN_NBLK) {
        // ------------- GEMM1 role: g_h0h = fp16(dinv * (x @ W1)) -------------
        __half (*Wt)[FIN + 8]  = reinterpret_cast<__half(*)[FIN + 8]>(dsm_);
        __half (*Ahs)[FIN + 8] = reinterpret_cast<__half(*)[FIN + 8]>(dsm_) + 64;

        for (int i = tid; i < FIN * 64; i += 1024) {
            int k = i >> 6, n = i & 63;
            Wt[n][k] = __float2half(W1[i]);
        }
        __syncthreads();

        const int g = tid >> 7;            // group 0..7 (128 threads each)
        const int t = tid & 127;
        const int warp = t >> 5, lane = t & 31;
        const int gr = lane >> 2;
        const int kc = (lane & 3) * 2;
        __half (*Ag)[FIN + 8] = Ahs + g * 64;
        const int barid = g + 1;

        for (int tile = (bid - SCAN_NBLK) * 8 + g; tile < NTILES; tile += GEMM_BLKS * 8) {
            const int rbase = tile * 64;
            #pragma unroll
            for (int it = 0; it < 16; it++) {
                int i = it * 128 + t;
                int r = i >> 5, v = i & 31;
                int R = rbase + r;
                float4 f = make_float4(0.f, 0.f, 0.f, 0.f);
                if (R < NN) f = reinterpret_cast<const float4*>(x + (size_t)R * FIN)[v];
                __half2 h01 = __floats2half2_rn(f.x, f.y);
                __half2 h23 = __floats2half2_rn(f.z, f.w);
                uint2 pk = make_uint2(*reinterpret_cast<uint32*>(&h01),
                                      *reinterpret_cast<uint32*>(&h23));
                *reinterpret_cast<uint2*>(&Ag[r][v * 4]) = pk;
            }
            asm volatile("bar.sync %0, 128;" :: "r"(barid) : "memory");

            const int lr0 = warp * 16 + gr, lr1 = lr0 + 8;
            const int R0 = rbase + lr0, R1 = rbase + lr1;
            float d[8][4];
            #pragma unroll
            for (int nt = 0; nt < 8; nt++)
                #pragma unroll
                for (int q = 0; q < 4; q++) d[nt][q] = 0.f;

            #pragma unroll
            for (int q = 0; q < FIN / 16; q++) {
                int k0 = q * 16 + kc;
                uint32 a0 = *reinterpret_cast<const uint32*>(&Ag[lr0][k0]);
                uint32 a1 = *reinterpret_cast<const uint32*>(&Ag[lr1][k0]);
                uint32 a2 = *reinterpret_cast<const uint32*>(&Ag[lr0][k0 + 8]);
                uint32 a3 = *reinterpret_cast<const uint32*>(&Ag[lr1][k0 + 8]);
                #pragma unroll
                for (int nt = 0; nt < 8; nt++) {
                    int n = nt * 8 + gr;
                    uint32 b0 = *reinterpret_cast<const uint32*>(&Wt[n][k0]);
                    uint32 b1 = *reinterpret_cast<const uint32*>(&Wt[n][k0 + 8]);
                    mma16816(d[nt], a0, a1, a2, a3, b0, b1);
                }
            }

            // premultiply by dinv computed from deg (fresh across launch boundary)
            float dv0 = (R0 < NN) ? rsqrtf((float)__ldcg(&g_deg[R0]) + 1.0f) : 0.f;
            float dv1 = (R1 < NN) ? rsqrtf((float)__ldcg(&g_deg[R1]) + 1.0f) : 0.f;
            #pragma unroll
            for (int nt = 0; nt < 8; nt++) {
                int c = nt * 8 + kc;
                *reinterpret_cast<__half2*>(&Ag[lr0][c]) =
                    __floats2half2_rn(d[nt][0] * dv0, d[nt][1] * dv0);
                *reinterpret_cast<__half2*>(&Ag[lr1][c]) =
                    __floats2half2_rn(d[nt][2] * dv1, d[nt][3] * dv1);
            }
            __syncwarp();
            __half* outp = reinterpret_cast<__half*>(g_h0h);
            #pragma unroll
            for (int rr = 0; rr < 16; rr++) {
                int R = rbase + warp * 16 + rr;
                if (R < NN) {
                    uint32 v = reinterpret_cast<const uint32*>(&Ag[warp * 16 + rr][0])[lane];
                    reinterpret_cast<uint32*>(outp + (size_t)R * 64)[lane] = v;
                }
            }
            asm volatile("bar.sync %0, 128;" :: "r"(barid) : "memory");
        }
        return;
    }

    // ---------------- CSR role (blocks 0..97): dinv + scan + fill ----------------
    int excl = 0;
    int valid = 0;
    {
        int i = bid * 1024 + tid;
        valid = (i < NN);
        int v = valid ? __ldcg(&g_deg[i]) : 0;
        if (valid) g_dinv[i] = rsqrtf((float)v + 1.0f);   // +1 self-loop
        int lane = tid & 31, wid = tid >> 5;
        int xs = v;
        #pragma unroll
        for (int dd = 1; dd < 32; dd <<= 1) {
            int y = __shfl_up_sync(0xffffffffu, xs, dd);
            if (lane >= dd) xs += y;
        }
        __shared__ int wsum[32];
        if (lane == 31) wsum[wid] = xs;
        __syncthreads();
        if (wid == 0) {
            int s = wsum[lane];
            int sx = s;
            #pragma unroll
            for (int dd = 1; dd < 32; dd <<= 1) {
                int y = __shfl_up_sync(0xffffffffu, sx, dd);
                if (lane >= dd) sx += y;
            }
            wsum[lane] = sx - s;
        }
        __syncthreads();
        int incl = xs + wsum[wid];
        excl = incl - v;
        if (tid == 1023) g_bsums[bid] = incl;
    }
    gbar(0);

    {
        __shared__ int ws[4];
        int v = 0, incl = 0;
        if (bid == 0) {
            if (tid < 128) {
                v = (tid < SCAN_NBLK) ? __ldcg(&g_bsums[tid]) : 0;
                int lane = tid & 31, wid = tid >> 5;
                int xs = v;
                #pragma unroll
                for (int dd = 1; dd < 32; dd <<= 1) {
                    int y = __shfl_up_sync(0xffffffffu, xs, dd);
                    if (lane >= dd) xs += y;
                }
                if (lane == 31) ws[wid] = xs;
                incl = xs;
            }
            __syncthreads();
            if (tid < 128) {
                int wid = tid >> 5;
                int off = 0;
                for (int w = 0; w < wid; w++) off += ws[w];
                incl += off;
                if (tid < SCAN_NBLK) g_bsums[tid] = incl - v;
            }
        }
    }
    gbar(1);

    if (valid) {
        int i = bid * 1024 + tid;
        g_rowptr[i] = excl + __ldcg(&g_bsums[bid]);
    }
    if (bid == 0 && tid == 0) g_rowptr[NN] = NE;
    gbar(2);

    // fill (atomic-free, no dinv gather): p = rowptr[col[e]] + rank[e]; payload = src*32
    const int gt = bid * 1024 + tid;
    for (int e = gt; e < NE; e += SCAN_NBLK * 1024) {
        int c = col[e];
        int p = __ldcg(&g_rowptr[c]) + __ldcg(&g_rank[e]);
        g_src[p] = row[e] << 5;
    }
}

// ---------------- conv2 tensor-core GEMM (premultiplied, fp16 A from g_h1h) ----------------
__global__ __launch_bounds__(128) void k_gemm2(const float* __restrict__ W) {
    __shared__ __half Wt[64][HID + 8];
    __shared__ __half Ahs[64][HID + 8];

    for (int i = threadIdx.x; i < HID * 64; i += 128) {
        int k = i >> 6, n = i & 63;
        Wt[n][k] = __float2half(W[i]);
    }

    const int rbase = blockIdx.x * 64;
    const __half* Ah = reinterpret_cast<const __half*>(g_h1h);
    #pragma unroll
    for (int it = 0; it < 4; it++) {
        int i = it * 128 + threadIdx.x;
        int r = i >> 3, v = i & 7;
        int R = rbase + r;
        uint4 val = make_uint4(0, 0, 0, 0);
        if (R < NN) val = reinterpret_cast<const uint4*>(Ah + (size_t)R * HID)[v];
        reinterpret_cast<uint4*>(&Ahs[r][0])[v] = val;
    }
    __syncthreads();

    const int warp = threadIdx.x >> 5, lane = threadIdx.x & 31;
    const int gr = lane >> 2;
    const int kc = (lane & 3) * 2;
    const int lr0 = warp * 16 + gr, lr1 = lr0 + 8;
    const int R0 = rbase + lr0, R1 = rbase + lr1;

    float d[8][4];
    #pragma unroll
    for (int nt = 0; nt < 8; nt++)
        #pragma unroll
        for (int q = 0; q < 4; q++) d[nt][q] = 0.f;

    #pragma unroll
    for (int q = 0; q < HID / 16; q++) {
        int k0 = q * 16 + kc;
        uint32 a0 = *reinterpret_cast<const uint32*>(&Ahs[lr0][k0]);
        uint32 a1 = *reinterpret_cast<const uint32*>(&Ahs[lr1][k0]);
        uint32 a2 = *reinterpret_cast<const uint32*>(&Ahs[lr0][k0 + 8]);
        uint32 a3 = *reinterpret_cast<const uint32*>(&Ahs[lr1][k0 + 8]);
        #pragma unroll
        for (int nt = 0; nt < 8; nt++) {
            int n = nt * 8 + gr;
            uint32 b0 = *reinterpret_cast<const uint32*>(&Wt[n][k0]);
            uint32 b1 = *reinterpret_cast<const uint32*>(&Wt[n][k0 + 8]);
            mma16816(d[nt], a0, a1, a2, a3, b0, b1);
        }
    }

    float dv0 = (R0 < NN) ? g_dinv[R0] : 0.f;
    float dv1 = (R1 < NN) ? g_dinv[R1] : 0.f;
    #pragma unroll
    for (int nt = 0; nt < 8; nt++) {
        int c = nt * 8 + kc;
        *reinterpret_cast<__half2*>(&Ahs[lr0][c]) =
            __floats2half2_rn(d[nt][0] * dv0, d[nt][1] * dv0);
        *reinterpret_cast<__half2*>(&Ahs[lr1][c]) =
            __floats2half2_rn(d[nt][2] * dv1, d[nt][3] * dv1);
    }
    __syncwarp();
    __half* outp = reinterpret_cast<__half*>(g_h0h);
    #pragma unroll
    for (int rr = 0; rr < 16; rr++) {
        int R = rbase + warp * 16 + rr;
        if (R < NN) {
            uint32 v = reinterpret_cast<const uint32*>(&Ahs[warp * 16 + rr][0])[lane];
            reinterpret_cast<uint32*>(outp + (size_t)R * 64)[lane] = v;
        }
    }
}

// ---------------- GCN aggregate (unweighted; both convs premultiplied) ----------------
// h[c] = relu(dinv[c] * (pre[c] + sum pre[s]) + b)
__global__ __launch_bounds__(256) void k_agg(const float* __restrict__ bias) {
    int gw = (blockIdx.x * 256 + threadIdx.x) >> 5;
    int lane = threadIdx.x & 31;
    float di = g_dinv[gw];
    int beg = g_rowptr[gw], end = g_rowptr[gw + 1];

    const __half2* hin = g_h0h;
    float2 hself = __half22float2(hin[gw * 32 + lane]);
    float ax = hself.x, ay = hself.y;

    int e = beg;
    for (; e + 8 <= end; e += 8) {
        int p[8];
        #pragma unroll
        for (int u = 0; u < 8; u++) p[u] = __ldg(&g_src[e + u]);
        float2 v[8];
        #pragma unroll
        for (int u = 0; u < 8; u++) v[u] = __half22float2(__ldg(&hin[p[u] + lane]));
        #pragma unroll
        for (int u = 0; u < 8; u++) {
            ax += v[u].x;
            ay += v[u].y;
        }
    }
    for (; e + 2 <= end; e += 2) {
        int p0 = __ldg(&g_src[e]);
        int p1 = __ldg(&g_src[e + 1]);
        float2 v0 = __half22float2(__ldg(&hin[p0 + lane]));
        float2 v1 = __half22float2(__ldg(&hin[p1 + lane]));
        ax += v0.x + v1.x;
        ay += v0.y + v1.y;
    }
    if (e < end) {
        int p = __ldg(&g_src[e]);
        float2 v = __half22float2(__ldg(&hin[p + lane]));
        ax += v.x;
        ay += v.y;
    }
    float2 b = reinterpret_cast<const float2*>(bias)[lane];
    float rx = fmaxf(fmaf(di, ax, b.x), 0.f);
    float ry = fmaxf(fmaf(di, ay, b.y), 0.f);
    g_h1h[gw * 32 + lane] = __floats2half2_rn(rx, ry);
}

// ---------------- edge head GEMM: g_y[r,16] = h2[r,64] @ Wm[64,16] (+bl on cols 0..7) ----------------
__global__ __launch_bounds__(128) void k_head(const float* __restrict__ Wl,
                                              const float* __restrict__ bl) {
    __shared__ __half Wt[16][HID + 8];     // Wm transposed [o][k]
    __shared__ __half Ahs[64][HID + 8];

    for (int i = threadIdx.x; i < 16 * 64; i += 128) {
        int o = i >> 6, k = i & 63;
        float wv = (o < 8) ? Wl[k * 8 + o] : Wl[(64 + k) * 8 + (o - 8)];
        Wt[o][k] = __float2half(wv);
    }

    const int rbase = blockIdx.x * 64;
    const __half* Ah = reinterpret_cast<const __half*>(g_h1h);
    #pragma unroll
    for (int it = 0; it < 4; it++) {
        int i = it * 128 + threadIdx.x;
        int r = i >> 3, v = i & 7;
        int R = rbase + r;
        uint4 val = make_uint4(0, 0, 0, 0);
        if (R < NN) val = reinterpret_cast<const uint4*>(Ah + (size_t)R * HID)[v];
        reinterpret_cast<uint4*>(&Ahs[r][0])[v] = val;
    }
    __syncthreads();

    const int warp = threadIdx.x >> 5, lane = threadIdx.x & 31;
    const int gr = lane >> 2;
    const int kc = (lane & 3) * 2;
    const int lr0 = warp * 16 + gr, lr1 = lr0 + 8;
    const int R0 = rbase + lr0, R1 = rbase + lr1;

    float d[2][4];
    #pragma unroll
    for (int nt = 0; nt < 2; nt++)
        #pragma unroll
        for (int q = 0; q < 4; q++) d[nt][q] = 0.f;

    #pragma unroll
    for (int q = 0; q < HID / 16; q++) {
        int k0 = q * 16 + kc;
        uint32 a0 = *reinterpret_cast<const uint32*>(&Ahs[lr0][k0]);
        uint32 a1 = *reinterpret_cast<const uint32*>(&Ahs[lr1][k0]);
        uint32 a2 = *reinterpret_cast<const uint32*>(&Ahs[lr0][k0 + 8]);
        uint32 a3 = *reinterpret_cast<const uint32*>(&Ahs[lr1][k0 + 8]);
        #pragma unroll
        for (int nt = 0; nt < 2; nt++) {
            int n = nt * 8 + gr;
            uint32 b0 = *reinterpret_cast<const uint32*>(&Wt[n][k0]);
            uint32 b1 = *reinterpret_cast<const uint32*>(&Wt[n][k0 + 8]);
            mma16816(d[nt], a0, a1, a2, a3, b0, b1);
        }
    }

    float bx0 = __ldg(&bl[kc]), bx1 = __ldg(&bl[kc + 1]);
    if (R0 < NN) {
        *reinterpret_cast<float2*>(&g_y[(size_t)R0 * 16 + kc]) =
            make_float2(d[0][0] + bx0, d[0][1] + bx1);
        *reinterpret_cast<float2*>(&g_y[(size_t)R0 * 16 + 8 + kc]) =
            make_float2(d[1][0], d[1][1]);
    }
    if (R1 < NN) {
        *reinterpret_cast<float2*>(&g_y[(size_t)R1 * 16 + kc]) =
            make_float2(d[0][2] + bx0, d[0][3] + bx1);
        *reinterpret_cast<float2*>(&g_y[(size_t)R1 * 16 + 8 + kc]) =
            make_float2(d[1][2], d[1][3]);
    }
}

// ---------------- edge phase + state cleanup for next replay ----------------
__global__ void k_edge(const int* __restrict__ row, const int* __restrict__ col,
                       float* __restrict__ out) {
    int idx = blockIdx.x * 256 + threadIdx.x;
    // cleanup for next graph replay (deg must be zero before k_hist; barc before gbar)
    if (idx < NN) g_deg[idx] = 0;
    if (idx < 8) g_barc[idx] = 0;
    if (idx >= NE * 2) return;
    int e = idx >> 1, c = idx & 1;
    int r = row[e], cl = col[e];
    const float4* y4 = reinterpret_cast<const float4*>(g_y);
    float4 a = y4[(size_t)r * 4 + c];
    float4 b = y4[(size_t)cl * 4 + 2 + c];
    float4 o;
    o.x = a.x + b.x; o.y = a.y + b.y; o.z = a.z + b.z; o.w = a.w + b.w;
    reinterpret_cast<float4*>(out)[idx] = o;
}

// ---------------- launch ----------------
extern "C" void kernel_launch(void* const* d_in, const int* in_sizes, int n_in,
                              void* d_out, int out_size) {
    const float* x  = (const float*)d_in[0];
    const int*   ei = (const int*)  d_in[1];
    const float* W1 = (const float*)d_in[2];
    const float* b1 = (const float*)d_in[3];
    const float* W2 = (const float*)d_in[4];
    const float* b2 = (const float*)d_in[5];
    const float* Wl = (const float*)d_in[6];
    const float* bl = (const float*)d_in[7];
    float* out = (float*)d_out;

    const int* row = ei;        // edge_index[0]
    const int* col = ei + NE;   // edge_index[1]

    const int DSMEM = (64 + 8 * 64) * (FIN + 8) * (int)sizeof(__half);  // 156,672 B
    static bool attr_set = false;
    if (!attr_set) {
        cudaFuncSetAttribute(k_scan_gemm, cudaFuncAttributeMaxDynamicSharedMemorySize, DSMEM);
        attr_set = true;
    }

    // degree histogram + per-edge rank (deg zeroed by previous k_edge / initial state)
    k_hist<<<ALL_B, 1024>>>(col);

    // fused: scan+fill (blocks 0..97) + premultiplied GEMM1 (blocks 98..147)
    k_scan_gemm<<<ALL_B, 1024, DSMEM>>>(row, col, x, W1);

    // conv1 agg (unweighted, premultiplied input) -> h1h
    k_agg<<<(NN * 32) / 256, 256>>>(b1);

    // conv2: premultiplied GEMM (h1h -> h0h) + agg (-> h1h)
    k_gemm2<<<NTILES, 128>>>(W2);
    k_agg<<<(NN * 32) / 256, 256>>>(b2);

    // edge head GEMM (h1h -> y), then per-edge sum (+cleanup)
    k_head<<<NTILES, 128>>>(Wl, bl);
    k_edge<<<(NE * 2 + 255) / 256, 256>>>(row, col, out);
}